// round 1
// baseline (speedup 1.0000x reference)
#include <cuda_runtime.h>
#include <cuda_bf16.h>
#include <cstdint>

// ---------------------------------------------------------------------------
// Problem constants
// ---------------------------------------------------------------------------
#define TT   64
#define BB   32
#define NTB  2048          // T*B
#define HID  256
#define NACT 12
#define FEAT 1152

// scratch sizes
#define A1_ELEMS (2048u*32*42*42)   // 115,605,504
#define A2_ELEMS (2048u*32*21*21)   // 28,901,376
#define A3_ELEMS (2048u*32*11*11)   // 7,929,856
#define XF_ELEMS (2048u*1152)
#define GI_ELEMS (2048u*768)
#define OUTS_ELEMS (2048u*256)

__device__ float g_a1[A1_ELEMS];
__device__ float g_a2[A2_ELEMS];
__device__ float g_a3[A3_ELEMS];
__device__ float g_xf[XF_ELEMS];
__device__ float g_gi[GI_ELEMS];
__device__ float g_outs[OUTS_ELEMS];
__device__ float g_h[2][BB*HID];

__device__ unsigned g_bar_cnt = 0;
__device__ unsigned g_bar_phase = 0;

// ---------------------------------------------------------------------------
// Fused conv3x3 (stride 2, pad 1) + bias + ELU.  One block per image.
// Input chunk staged in smem; weights staged transposed [k][oc] so each
// thread does 1 scalar input LDS + 1 float4 weight LDS per 4 FMAs.
// ---------------------------------------------------------------------------
template<int IC, int IH, int OH, int ICCHUNK, int NT>
__global__ void conv_elu(const float* __restrict__ in, const float* __restrict__ wgt,
                         const float* __restrict__ bias, float* __restrict__ out) {
    constexpr int OC = 32;
    constexpr int OHW = OH*OH;
    constexpr int NITEMS = (OC/4) * OHW;       // work item = 4 out-channels x 1 pixel
    constexpr int NCHUNK = IC / ICCHUNK;
    constexpr int INCH = ICCHUNK*IH*IH;        // floats in smem input chunk
    constexpr int WCH  = ICCHUNK*9*OC;         // floats in smem weight chunk

    extern __shared__ float sm[];
    float* s_in = sm;
    float* s_w  = sm + INCH;

    const int n   = blockIdx.x;
    const int tid = threadIdx.x;
    const float* inN = in + (size_t)n * (IC*IH*IH);
    float* outN = out + (size_t)n * (OC*OHW);

    auto load_chunk = [&](int c0) {
        const float4* src = reinterpret_cast<const float4*>(inN + c0*IH*IH);
        float4* dst = reinterpret_cast<float4*>(s_in);
        for (int i = tid; i < INCH/4; i += NT) dst[i] = src[i];
        for (int i = tid; i < WCH; i += NT) {
            int oc = i / (ICCHUNK*9);
            int kk = i - oc*(ICCHUNK*9);
            s_w[kk*OC + oc] = wgt[(oc*IC + c0 + kk/9)*9 + (kk - (kk/9)*9)];
        }
    };

    auto item_accum = [&](int idx, float* a4) {
        int ocg = idx / OHW;
        int sp  = idx - ocg*OHW;
        int oy = sp / OH, ox = sp - oy*OH;
        int iy0 = 2*oy - 1, ix0 = 2*ox - 1;
        const float* swp = s_w + ocg*4;
        #pragma unroll 4
        for (int ic = 0; ic < ICCHUNK; ic++) {
            const float* sI = s_in + ic*IH*IH;
            #pragma unroll
            for (int ky = 0; ky < 3; ky++) {
                int iy = iy0 + ky;
                if ((unsigned)iy < (unsigned)IH) {
                    #pragma unroll
                    for (int kx = 0; kx < 3; kx++) {
                        int ix = ix0 + kx;
                        float v = ((unsigned)ix < (unsigned)IH) ? sI[iy*IH + ix] : 0.f;
                        float4 w4 = *reinterpret_cast<const float4*>(swp + (ic*9 + ky*3 + kx)*OC);
                        a4[0] += v*w4.x; a4[1] += v*w4.y; a4[2] += v*w4.z; a4[3] += v*w4.w;
                    }
                }
            }
        }
    };

    auto store_item = [&](int idx, const float* a4) {
        int ocg = idx / OHW;
        int sp  = idx - ocg*OHW;
        #pragma unroll
        for (int j = 0; j < 4; j++) {
            float x = a4[j] + bias[ocg*4 + j];
            outN[(ocg*4 + j)*OHW + sp] = (x > 0.f) ? x : expm1f(x);
        }
    };

    if constexpr (NCHUNK == 1) {
        load_chunk(0);
        __syncthreads();
        for (int idx = tid; idx < NITEMS; idx += NT) {
            float a4[4] = {0.f, 0.f, 0.f, 0.f};
            item_accum(idx, a4);
            store_item(idx, a4);
        }
    } else {
        constexpr int NPT = (NITEMS + NT - 1) / NT;
        float acc[NPT][4];
        #pragma unroll
        for (int i = 0; i < NPT; i++)
            #pragma unroll
            for (int j = 0; j < 4; j++) acc[i][j] = 0.f;
        for (int c = 0; c < NCHUNK; c++) {
            if (c) __syncthreads();
            load_chunk(c*ICCHUNK);
            __syncthreads();
            #pragma unroll 1
            for (int it = 0; it < NPT; it++) {
                int idx = tid + it*NT;
                if (idx < NITEMS) item_accum(idx, acc[it]);
            }
        }
        #pragma unroll 1
        for (int it = 0; it < NPT; it++) {
            int idx = tid + it*NT;
            if (idx < NITEMS) store_item(idx, acc[it]);
        }
    }
}

// ---------------------------------------------------------------------------
// gi = X[2048,1152] @ W_ih[768,1152]^T + b_ih   (both operands K-major, NT GEMM)
// 64x64 tile, BK=16, 256 threads, 4x4 micro-tile.
// ---------------------------------------------------------------------------
__global__ void gemm_xWih(const float* __restrict__ A, const float* __restrict__ B,
                          const float* __restrict__ bias, float* __restrict__ C) {
    __shared__ float As[16][68];   // row stride 68 floats = 272B (16B aligned)
    __shared__ float Bs[16][68];
    const int bm = blockIdx.y * 64;
    const int bn = blockIdx.x * 64;
    const int tid = threadIdx.x;
    const int tx = tid & 15, ty = tid >> 4;
    float acc[4][4];
    #pragma unroll
    for (int i = 0; i < 4; i++)
        #pragma unroll
        for (int j = 0; j < 4; j++) acc[i][j] = 0.f;

    const int lr = tid >> 2;            // 0..63
    const int lk = (tid & 3) * 4;       // 0,4,8,12

    for (int k0 = 0; k0 < FEAT; k0 += 16) {
        float4 av = *reinterpret_cast<const float4*>(&A[(size_t)(bm + lr)*FEAT + k0 + lk]);
        float4 bv = *reinterpret_cast<const float4*>(&B[(size_t)(bn + lr)*FEAT + k0 + lk]);
        As[lk+0][lr] = av.x; As[lk+1][lr] = av.y; As[lk+2][lr] = av.z; As[lk+3][lr] = av.w;
        Bs[lk+0][lr] = bv.x; Bs[lk+1][lr] = bv.y; Bs[lk+2][lr] = bv.z; Bs[lk+3][lr] = bv.w;
        __syncthreads();
        #pragma unroll
        for (int k = 0; k < 16; k++) {
            float4 a4 = *reinterpret_cast<const float4*>(&As[k][ty*4]);
            float4 b4 = *reinterpret_cast<const float4*>(&Bs[k][tx*4]);
            float a[4] = {a4.x, a4.y, a4.z, a4.w};
            float b[4] = {b4.x, b4.y, b4.z, b4.w};
            #pragma unroll
            for (int i = 0; i < 4; i++)
                #pragma unroll
                for (int j = 0; j < 4; j++) acc[i][j] += a[i]*b[j];
        }
        __syncthreads();
    }
    #pragma unroll
    for (int i = 0; i < 4; i++) {
        int m = bm + ty*4 + i;
        #pragma unroll
        for (int j = 0; j < 4; j++) {
            int nn = bn + tx*4 + j;
            C[(size_t)m*768 + nn] = acc[i][j] + bias[nn];
        }
    }
}

// ---------------------------------------------------------------------------
// Persistent GRU kernel: 64 blocks x 384 threads, one grid barrier per step.
// Block bx owns output columns g' = bx*4 .. bx*4+3 (all 3 gates for them),
// so the gate combine is block-local -> single barrier/step.
// h double-buffered in global; reads bypass L1 (__ldcg).
// ---------------------------------------------------------------------------
#define GRU_BLOCKS 64
#define GRU_THREADS 384

__device__ __forceinline__ void grid_barrier(unsigned target) {
    __threadfence();
    __syncthreads();
    if (threadIdx.x == 0) {
        unsigned v = atomicAdd(&g_bar_cnt, 1);
        if (v == GRU_BLOCKS - 1) {
            g_bar_cnt = 0;
            __threadfence();
            atomicAdd(&g_bar_phase, 1);
        } else {
            while ((int)(*(volatile unsigned*)&g_bar_phase - target) < 0) { __nanosleep(32); }
        }
        __threadfence();
    }
    __syncthreads();
}

__global__ void gru_kernel(const float* __restrict__ rnn_in, const float* __restrict__ mask,
                           const float* __restrict__ W_hh, const float* __restrict__ b_hh,
                           const float* __restrict__ gi_all, float* __restrict__ outs,
                           float* __restrict__ hfin) {
    __shared__ float s_w[12*256];     // 12 W_hh rows for this block
    __shared__ float s_h[BB*HID];     // transposed: s_h[k*32 + b]
    __shared__ float s_gh[384];
    __shared__ float s_bhh[12];

    const int tid = threadIdx.x;
    const int bx  = blockIdx.x;

    for (int i = tid; i < 12*256; i += GRU_THREADS) {
        int rl = i >> 8, k = i & 255;
        int gate = rl >> 2, gj = rl & 3;
        s_w[i] = W_hh[(size_t)(gate*256 + bx*4 + gj)*256 + k];
    }
    if (tid < 12) {
        int gate = tid >> 2, gj = tid & 3;
        s_bhh[tid] = b_hh[gate*256 + bx*4 + gj];
    }
    if (bx == 0) {
        for (int i = tid; i < BB*HID; i += GRU_THREADS) g_h[0][i] = rnn_in[i];
    }
    unsigned tgt = *(volatile unsigned*)&g_bar_phase;
    grid_barrier(++tgt);

    for (int t = 0; t < TT; t++) {
        const float* hprev = g_h[t & 1];
        // masked h -> smem (transposed)
        for (int i = tid; i < BB*HID; i += GRU_THREADS) {
            int b = i >> 8, k = i & 255;
            s_h[k*32 + b] = __ldcg(&hprev[i]) * __ldg(&mask[t*32 + b]);
        }
        __syncthreads();
        {
            int gate = tid / 128;
            int r    = tid - gate*128;
            int gj   = r >> 5, b = r & 31;
            int rl   = gate*4 + gj;
            const float* wrow = s_w + rl*256;
            float acc = s_bhh[rl];
            #pragma unroll 8
            for (int k = 0; k < 256; k++) acc += s_h[k*32 + b] * wrow[k];
            s_gh[tid] = acc;
        }
        __syncthreads();
        if (tid < 128) {
            int gj = tid >> 5, b = tid & 31;
            int g  = bx*4 + gj;
            const float* gi = gi_all + (size_t)(t*32 + b)*768;
            float ghr = s_gh[0*128 + gj*32 + b];
            float ghz = s_gh[1*128 + gj*32 + b];
            float ghn = s_gh[2*128 + gj*32 + b];
            float rr = 1.f / (1.f + expf(-(__ldg(&gi[g])       + ghr)));
            float zz = 1.f / (1.f + expf(-(__ldg(&gi[256 + g]) + ghz)));
            float nn = tanhf(__ldg(&gi[512 + g]) + rr*ghn);
            float hold = s_h[g*32 + b];                 // masked h
            float hn = (1.f - zz)*nn + zz*hold;
            g_h[(t + 1) & 1][b*256 + g] = hn;
            outs[(size_t)(t*32 + b)*256 + g] = hn;
            if (t == TT - 1) hfin[b*256 + g] = hn;
        }
        grid_barrier(++tgt);
    }
}

// ---------------------------------------------------------------------------
// Heads: one warp per row of outs[2048,256].
// d_out layout: [0:2048) v | [2048:4096) actions(float) | [4096:6144) logp_a |
//               [6144:8192) ent | [8192:16384) h_final
// ---------------------------------------------------------------------------
__global__ void heads_kernel(const float* __restrict__ outs, const int* __restrict__ actions,
                             const float* __restrict__ Wc, const float* __restrict__ bc,
                             const float* __restrict__ Wa, const float* __restrict__ ba,
                             float* __restrict__ d_out) {
    int warp = (blockIdx.x * blockDim.x + threadIdx.x) >> 5;
    int lane = threadIdx.x & 31;
    if (warp >= NTB) return;
    const float* o = outs + (size_t)warp * 256;

    float acc[13];
    #pragma unroll
    for (int g = 0; g < 13; g++) acc[g] = 0.f;
    #pragma unroll
    for (int i = 0; i < 8; i++) {
        int k = lane + 32*i;
        float x = o[k];
        acc[0] += x * __ldg(&Wc[k]);
        #pragma unroll
        for (int g = 0; g < 12; g++) acc[1 + g] += x * __ldg(&Wa[g*256 + k]);
    }
    #pragma unroll
    for (int g = 0; g < 13; g++) {
        #pragma unroll
        for (int s = 16; s > 0; s >>= 1) acc[g] += __shfl_xor_sync(0xFFFFFFFFu, acc[g], s);
    }
    if (lane == 0) {
        float v = acc[0] + bc[0];
        float l[12];
        float m = -1e30f;
        #pragma unroll
        for (int g = 0; g < 12; g++) { l[g] = acc[1 + g] + ba[g]; m = fmaxf(m, l[g]); }
        float s = 0.f, sl = 0.f;
        #pragma unroll
        for (int g = 0; g < 12; g++) {
            float e = expf(l[g] - m);
            s += e; sl += e * l[g];
        }
        float logZ = m + logf(s);
        int a = actions[warp];
        d_out[warp]        = v;
        d_out[2048 + warp] = (float)a;
        d_out[4096 + warp] = l[a] - logZ;
        d_out[6144 + warp] = logZ - sl / s;
    }
}

// ---------------------------------------------------------------------------
// Host launcher
// ---------------------------------------------------------------------------
#define SMEM1 ((4*84*84  + 4*9*32 )*4)   // 117,504
#define SMEM2 ((16*42*42 + 16*9*32)*4)   // 131,328
#define SMEM3 ((32*21*21 + 32*9*32)*4)   //  93,312
#define SMEM4 ((32*11*11 + 32*9*32)*4)   //  52,352

extern "C" void kernel_launch(void* const* d_in, const int* in_sizes, int n_in,
                              void* d_out, int out_size) {
    const float* inputs = (const float*)d_in[0];
    const float* rnn_in = (const float*)d_in[1];
    const float* mask   = (const float*)d_in[2];
    const int*   actions= (const int*)  d_in[3];
    const float* w1 = (const float*)d_in[4];  const float* b1 = (const float*)d_in[5];
    const float* w2 = (const float*)d_in[6];  const float* b2 = (const float*)d_in[7];
    const float* w3 = (const float*)d_in[8];  const float* b3 = (const float*)d_in[9];
    const float* w4 = (const float*)d_in[10]; const float* b4 = (const float*)d_in[11];
    const float* W_ih = (const float*)d_in[12];
    const float* W_hh = (const float*)d_in[13];
    const float* b_ih = (const float*)d_in[14];
    const float* b_hh = (const float*)d_in[15];
    const float* Wc = (const float*)d_in[16]; const float* bc = (const float*)d_in[17];
    const float* Wa = (const float*)d_in[18]; const float* ba = (const float*)d_in[19];
    float* out = (float*)d_out;

    float *a1, *a2, *a3, *xf, *gi, *outs;
    cudaGetSymbolAddress((void**)&a1, g_a1);
    cudaGetSymbolAddress((void**)&a2, g_a2);
    cudaGetSymbolAddress((void**)&a3, g_a3);
    cudaGetSymbolAddress((void**)&xf, g_xf);
    cudaGetSymbolAddress((void**)&gi, g_gi);
    cudaGetSymbolAddress((void**)&outs, g_outs);

    cudaFuncSetAttribute(conv_elu<4,84,42,4,512>,   cudaFuncAttributeMaxDynamicSharedMemorySize, SMEM1);
    cudaFuncSetAttribute(conv_elu<32,42,21,16,512>, cudaFuncAttributeMaxDynamicSharedMemorySize, SMEM2);
    cudaFuncSetAttribute(conv_elu<32,21,11,32,512>, cudaFuncAttributeMaxDynamicSharedMemorySize, SMEM3);
    cudaFuncSetAttribute(conv_elu<32,11,6,32,512>,  cudaFuncAttributeMaxDynamicSharedMemorySize, SMEM4);

    conv_elu<4,84,42,4,512>  <<<NTB, 512, SMEM1>>>(inputs, w1, b1, a1);
    conv_elu<32,42,21,16,512><<<NTB, 512, SMEM2>>>(a1, w2, b2, a2);
    conv_elu<32,21,11,32,512><<<NTB, 512, SMEM3>>>(a2, w3, b3, a3);
    conv_elu<32,11,6,32,512> <<<NTB, 512, SMEM4>>>(a3, w4, b4, xf);

    gemm_xWih<<<dim3(768/64, 2048/64), 256>>>(xf, W_ih, b_ih, gi);

    gru_kernel<<<GRU_BLOCKS, GRU_THREADS>>>(rnn_in, mask, W_hh, b_hh, gi, outs, out + 8192);

    heads_kernel<<<256, 256>>>(outs, actions, Wc, bc, Wa, ba, out);
}

// round 2
// speedup vs baseline: 1.8111x; 1.8111x over previous
#include <cuda_runtime.h>
#include <cuda_bf16.h>
#include <cstdint>

// ---------------------------------------------------------------------------
// Problem constants
// ---------------------------------------------------------------------------
#define TT   64
#define BB   32
#define NTB  2048
#define HID  256
#define FEAT 1152

__device__ float g_a1[2048u*32*42*42];   // NHWC
__device__ float g_a2[2048u*32*21*21];   // NHWC
__device__ float g_a3[2048u*32*11*11];   // NHWC
__device__ float g_xf[2048u*1152];       // reference feature order
__device__ float g_gi[2048u*768];
__device__ float g_outs[2048u*256];
__device__ float g_h[2][BB*HID];
__device__ unsigned g_bar_cnt = 0;
__device__ unsigned g_bar_phase = 0;

// ---------------------------------------------------------------------------
// tf32 helpers
// ---------------------------------------------------------------------------
__device__ __forceinline__ float tf32r(float f) {
    uint32_t u; asm("cvt.rna.tf32.f32 %0, %1;" : "=r"(u) : "f"(f));
    return __uint_as_float(u);
}
__device__ __forceinline__ void mma8(float4& d, float a0, float a1, float a2, float a3,
                                     float b0, float b1) {
    asm volatile("mma.sync.aligned.m16n8k8.row.col.f32.tf32.tf32.f32 "
        "{%0,%1,%2,%3},{%4,%5,%6,%7},{%8,%9},{%0,%1,%2,%3};"
        : "+f"(d.x), "+f"(d.y), "+f"(d.z), "+f"(d.w)
        : "r"(__float_as_uint(a0)), "r"(__float_as_uint(a1)),
          "r"(__float_as_uint(a2)), "r"(__float_as_uint(a3)),
          "r"(__float_as_uint(b0)), "r"(__float_as_uint(b1)));
}
__device__ __forceinline__ float eluf(float x) { return x > 0.f ? x : expm1f(x); }

// ---------------------------------------------------------------------------
// Implicit-GEMM conv3x3 stride2 pad1, OC=32, tf32 mma.
// Block = (image, band of BAND output rows). 256 threads = 8 warps
//   = 2 (m16 halves of OC=32) x 4 (pixel-tile groups of 8 pixels).
// Activations NHWC; IC=32 path uses grouped layout [y][icgrp][x]*9+ic8 so
// B-fragments are contiguous ic-runs with stride-9 anti-conflict padding.
// Everything stored in smem pre-converted to tf32 (RNA).
// ---------------------------------------------------------------------------
template<int IC, int IH, int OH, int BAND, bool IN_NCHW, bool OUT_REF>
__global__ void __launch_bounds__(256) conv_mma(const float* __restrict__ in,
        const float* __restrict__ wgt, const float* __restrict__ bias,
        float* __restrict__ out)
{
    constexpr int OW = OH, IW = IH;
    constexpr bool C1 = (IC == 4);
    constexpr int G  = C1 ? 1 : IC/8;
    constexpr int KS = C1 ? 6 : (IC*9)/8;        // k8 steps
    constexpr int KW = C1 ? 48 : IC*9;           // padded K per oc row
    constexpr int AS = KW + 4;                   // weight row stride (conflict-free)
    constexpr int ROWS = 2*BAND + 1;
    constexpr int RW = C1 ? (IW+2)*4 : G*(IW+2)*9;  // floats per input row
    constexpr int SIN = ROWS*RW;
    constexpr int NPIX = BAND*OW;
    constexpr int NT8 = (NPIX+7)/8;
    constexpr int NTW = (NT8+3)/4;
    constexpr int OHW = OH*OW;

    extern __shared__ float sm[];
    float* s_in = sm;
    float* s_w  = sm + SIN;

    const int tid = threadIdx.x;
    const int n = blockIdx.x;
    const int oy0 = blockIdx.y * BAND;
    const int ybase = 2*oy0 - 1;

    for (int i = tid; i < SIN; i += 256) s_in[i] = 0.f;
    __syncthreads();

    // ---- stage weights (k-major per oc, tf32) ----
    if (C1) {
        for (int i = tid; i < 32*48; i += 256) {
            int oc = i/48, r = i - oc*48;
            int ky = r>>4, rr = r&15, kx = rr>>2, ic = rr&3;
            float v = (kx < 3) ? wgt[((oc*4+ic)*3+ky)*3+kx] : 0.f;
            s_w[oc*AS + r] = tf32r(v);
        }
    } else {
        for (int i = tid; i < 32*288; i += 256) {
            int oc = i/288, r = i - oc*288;
            int s = r>>3, ii = r&7;
            int tap = s>>2, g = s&3, ic = g*8+ii, ky = tap/3, kx = tap - ky*3;
            s_w[oc*AS + r] = tf32r(wgt[((oc*IC+ic)*3+ky)*3+kx]);
        }
    }
    // ---- stage input band (tf32, halo already zeroed) ----
    {
        int y_lo = ybase < 0 ? 0 : ybase;
        int y_hi = ybase + ROWS - 1; if (y_hi > IH-1) y_hi = IH-1;
        int nrows = y_hi - y_lo + 1;
        if (IN_NCHW) {
            for (int i = tid; i < nrows*IW*IC; i += 256) {
                int x = i % IW; int t2 = i / IW; int yy = t2 % nrows; int c = t2 / nrows;
                int y = y_lo + yy;
                float v = in[(((size_t)n*IC + c)*IH + y)*IW + x];
                s_in[(y - ybase)*RW + (x+1)*4 + c] = tf32r(v);
            }
        } else {
            for (int i = tid; i < nrows*IW*IC; i += 256) {
                int c = i & (IC-1); int t2 = i / IC; int x = t2 % IW; int yy = t2 / IW;
                int y = y_lo + yy;
                float v = in[(((size_t)n*IH + y)*IW + x)*IC + c];
                s_in[(y - ybase)*RW + ((c>>3)*(IW+2) + x + 1)*9 + (c&7)] = tf32r(v);
            }
        }
    }
    __syncthreads();

    const int lane = tid & 31, warp = tid >> 5;
    const int m0 = (warp & 1)*16;
    const int ng = warp >> 1;
    const int gq = lane >> 2, tq = lane & 3;

    int pixbase[NTW];
    #pragma unroll
    for (int j = 0; j < NTW; j++) {
        int tile = ng + 4*j;
        int p = tile*8 + gq;
        int pp = (p < NPIX && tile < NT8) ? p : 0;
        int dy = pp / OW, ox = pp - dy*OW;
        pixbase[j] = C1 ? (2*dy*RW + 8*ox + tq) : (2*dy*RW + 18*ox + tq);
    }

    float4 acc[NTW];
    #pragma unroll
    for (int j = 0; j < NTW; j++) acc[j] = make_float4(0.f,0.f,0.f,0.f);

    const float* swr = s_w + (m0 + gq)*AS + tq;
    #pragma unroll
    for (int s = 0; s < KS; s++) {
        float a0 = swr[s*8];
        float a1 = swr[s*8 + 8*AS];
        float a2 = swr[s*8 + 4];
        float a3 = swr[s*8 + 8*AS + 4];
        int uoff;
        if (C1) { int ky = s>>1, h = s&1; uoff = ky*RW + h*8; }
        else    { int tap = s>>2, g = s&3; int ky = tap/3, kx = tap - ky*3;
                  uoff = ky*RW + (g*(IW+2)+kx)*9; }
        #pragma unroll
        for (int j = 0; j < NTW; j++) {
            const float* bp = s_in + pixbase[j] + uoff;
            mma8(acc[j], a0, a1, a2, a3, bp[0], bp[4]);
        }
    }

    const float b0v = __ldg(&bias[m0+gq]);
    const float b8v = __ldg(&bias[m0+gq+8]);
    #pragma unroll
    for (int j = 0; j < NTW; j++) {
        int tile = ng + 4*j;
        if (tile >= NT8) continue;
        int pc = tile*8 + tq*2;
        int oc = m0 + gq;
        int gp = oy0*OW + pc;
        float v0 = eluf(acc[j].x + b0v);
        float v1 = eluf(acc[j].y + b0v);
        float v2 = eluf(acc[j].z + b8v);
        float v3 = eluf(acc[j].w + b8v);
        if (OUT_REF) {
            float* ob = out + (size_t)n*1152;
            if (pc   < NPIX) { ob[oc*36 + gp]     = v0; ob[(oc+8)*36 + gp]     = v2; }
            if (pc+1 < NPIX) { ob[oc*36 + gp + 1] = v1; ob[(oc+8)*36 + gp + 1] = v3; }
        } else {
            float* ob = out + ((size_t)n*OHW + gp)*32;
            if (pc   < NPIX) { ob[oc]      = v0; ob[oc+8]      = v2; }
            if (pc+1 < NPIX) { ob[32 + oc] = v1; ob[32 + oc+8] = v3; }
        }
    }
}

// ---------------------------------------------------------------------------
// gi[2048,768] = xf[2048,1152] @ W_ih[768,1152]^T + b_ih    (tf32 mma)
// block 64x64, 8 warps = 2m x 4n, warp tile 32x16, k-chunk 16.
// ---------------------------------------------------------------------------
__global__ void __launch_bounds__(256) gemm_tf32(const float* __restrict__ A,
        const float* __restrict__ B, const float* __restrict__ bias,
        float* __restrict__ C)
{
    constexpr int KCP = 20;
    __shared__ float As[64*KCP], Bs[64*KCP];
    const int bm = blockIdx.y*64, bn = blockIdx.x*64;
    const int tid = threadIdx.x, lane = tid&31, warp = tid>>5;
    const int wm = (warp&1)*32, wn = (warp>>1)*16;
    const int gq = lane>>2, tq = lane&3;
    const int ldr = tid>>2, ldk = (tid&3)*4;

    float4 acc[2][2];
    #pragma unroll
    for (int i = 0; i < 2; i++)
        #pragma unroll
        for (int j = 0; j < 2; j++) acc[i][j] = make_float4(0.f,0.f,0.f,0.f);

    for (int k0 = 0; k0 < FEAT; k0 += 16) {
        float4 av = *(const float4*)(A + (size_t)(bm+ldr)*FEAT + k0 + ldk);
        float4 bv = *(const float4*)(B + (size_t)(bn+ldr)*FEAT + k0 + ldk);
        av.x = tf32r(av.x); av.y = tf32r(av.y); av.z = tf32r(av.z); av.w = tf32r(av.w);
        bv.x = tf32r(bv.x); bv.y = tf32r(bv.y); bv.z = tf32r(bv.z); bv.w = tf32r(bv.w);
        *(float4*)(As + ldr*KCP + ldk) = av;
        *(float4*)(Bs + ldr*KCP + ldk) = bv;
        __syncthreads();
        #pragma unroll
        for (int ks = 0; ks < 2; ks++) {
            #pragma unroll
            for (int mi = 0; mi < 2; mi++) {
                const float* ap = As + (wm + mi*16 + gq)*KCP + ks*8 + tq;
                float a0 = ap[0], a1 = ap[8*KCP], a2 = ap[4], a3 = ap[8*KCP+4];
                #pragma unroll
                for (int ni = 0; ni < 2; ni++) {
                    const float* bp = Bs + (wn + ni*8 + gq)*KCP + ks*8 + tq;
                    mma8(acc[mi][ni], a0, a1, a2, a3, bp[0], bp[4]);
                }
            }
        }
        __syncthreads();
    }
    #pragma unroll
    for (int mi = 0; mi < 2; mi++) {
        #pragma unroll
        for (int ni = 0; ni < 2; ni++) {
            int row = bm + wm + mi*16 + gq;
            int col = bn + wn + ni*8 + tq*2;
            float bb0 = __ldg(&bias[col]), bb1 = __ldg(&bias[col+1]);
            C[(size_t)row*768 + col]       = acc[mi][ni].x + bb0;
            C[(size_t)row*768 + col + 1]   = acc[mi][ni].y + bb1;
            C[(size_t)(row+8)*768 + col]   = acc[mi][ni].z + bb0;
            C[(size_t)(row+8)*768 + col+1] = acc[mi][ni].w + bb1;
        }
    }
}

// ---------------------------------------------------------------------------
// Persistent GRU (unchanged from R1 — profiled next round)
// ---------------------------------------------------------------------------
#define GRU_BLOCKS 64
#define GRU_THREADS 384

__device__ __forceinline__ void grid_barrier(unsigned target) {
    __threadfence();
    __syncthreads();
    if (threadIdx.x == 0) {
        unsigned v = atomicAdd(&g_bar_cnt, 1);
        if (v == GRU_BLOCKS - 1) {
            g_bar_cnt = 0;
            __threadfence();
            atomicAdd(&g_bar_phase, 1);
        } else {
            while ((int)(*(volatile unsigned*)&g_bar_phase - target) < 0) { __nanosleep(32); }
        }
        __threadfence();
    }
    __syncthreads();
}

__global__ void gru_kernel(const float* __restrict__ rnn_in, const float* __restrict__ mask,
                           const float* __restrict__ W_hh, const float* __restrict__ b_hh,
                           const float* __restrict__ gi_all, float* __restrict__ outs,
                           float* __restrict__ hfin) {
    __shared__ float s_w[12*256];
    __shared__ float s_h[BB*HID];
    __shared__ float s_gh[384];
    __shared__ float s_bhh[12];

    const int tid = threadIdx.x;
    const int bx  = blockIdx.x;

    for (int i = tid; i < 12*256; i += GRU_THREADS) {
        int rl = i >> 8, k = i & 255;
        int gate = rl >> 2, gj = rl & 3;
        s_w[i] = W_hh[(size_t)(gate*256 + bx*4 + gj)*256 + k];
    }
    if (tid < 12) {
        int gate = tid >> 2, gj = tid & 3;
        s_bhh[tid] = b_hh[gate*256 + bx*4 + gj];
    }
    if (bx == 0) {
        for (int i = tid; i < BB*HID; i += GRU_THREADS) g_h[0][i] = rnn_in[i];
    }
    unsigned tgt = *(volatile unsigned*)&g_bar_phase;
    grid_barrier(++tgt);

    for (int t = 0; t < TT; t++) {
        const float* hprev = g_h[t & 1];
        for (int i = tid; i < BB*HID; i += GRU_THREADS) {
            int b = i >> 8, k = i & 255;
            s_h[k*32 + b] = __ldcg(&hprev[i]) * __ldg(&mask[t*32 + b]);
        }
        __syncthreads();
        {
            int gate = tid / 128;
            int r    = tid - gate*128;
            int gj   = r >> 5, b = r & 31;
            int rl   = gate*4 + gj;
            const float* wrow = s_w + rl*256;
            float acc = s_bhh[rl];
            #pragma unroll 8
            for (int k = 0; k < 256; k++) acc += s_h[k*32 + b] * wrow[k];
            s_gh[tid] = acc;
        }
        __syncthreads();
        if (tid < 128) {
            int gj = tid >> 5, b = tid & 31;
            int g  = bx*4 + gj;
            const float* gi = gi_all + (size_t)(t*32 + b)*768;
            float ghr = s_gh[0*128 + gj*32 + b];
            float ghz = s_gh[1*128 + gj*32 + b];
            float ghn = s_gh[2*128 + gj*32 + b];
            float rr = 1.f / (1.f + expf(-(__ldg(&gi[g])       + ghr)));
            float zz = 1.f / (1.f + expf(-(__ldg(&gi[256 + g]) + ghz)));
            float nn = tanhf(__ldg(&gi[512 + g]) + rr*ghn);
            float hold = s_h[g*32 + b];
            float hn = (1.f - zz)*nn + zz*hold;
            g_h[(t + 1) & 1][b*256 + g] = hn;
            outs[(size_t)(t*32 + b)*256 + g] = hn;
            if (t == TT - 1) hfin[b*256 + g] = hn;
        }
        grid_barrier(++tgt);
    }
}

// ---------------------------------------------------------------------------
// Heads (unchanged)
// ---------------------------------------------------------------------------
__global__ void heads_kernel(const float* __restrict__ outs, const int* __restrict__ actions,
                             const float* __restrict__ Wc, const float* __restrict__ bc,
                             const float* __restrict__ Wa, const float* __restrict__ ba,
                             float* __restrict__ d_out) {
    int warp = (blockIdx.x * blockDim.x + threadIdx.x) >> 5;
    int lane = threadIdx.x & 31;
    if (warp >= NTB) return;
    const float* o = outs + (size_t)warp * 256;

    float acc[13];
    #pragma unroll
    for (int g = 0; g < 13; g++) acc[g] = 0.f;
    #pragma unroll
    for (int i = 0; i < 8; i++) {
        int k = lane + 32*i;
        float x = o[k];
        acc[0] += x * __ldg(&Wc[k]);
        #pragma unroll
        for (int g = 0; g < 12; g++) acc[1 + g] += x * __ldg(&Wa[g*256 + k]);
    }
    #pragma unroll
    for (int g = 0; g < 13; g++) {
        #pragma unroll
        for (int s = 16; s > 0; s >>= 1) acc[g] += __shfl_xor_sync(0xFFFFFFFFu, acc[g], s);
    }
    if (lane == 0) {
        float v = acc[0] + bc[0];
        float l[12];
        float m = -1e30f;
        #pragma unroll
        for (int g = 0; g < 12; g++) { l[g] = acc[1 + g] + ba[g]; m = fmaxf(m, l[g]); }
        float s = 0.f, sl = 0.f;
        #pragma unroll
        for (int g = 0; g < 12; g++) {
            float e = expf(l[g] - m);
            s += e; sl += e * l[g];
        }
        float logZ = m + logf(s);
        int a = actions[warp];
        d_out[warp]        = v;
        d_out[2048 + warp] = (float)a;
        d_out[4096 + warp] = l[a] - logZ;
        d_out[6144 + warp] = logZ - sl / s;
    }
}

// ---------------------------------------------------------------------------
// Host launcher
// ---------------------------------------------------------------------------
// smem sizes (floats): SIN + 32*AS
#define C1_SMEM ((13*344            + 32*52 ) * 4)
#define C2_SMEM ((15*(4*44*9)       + 32*292) * 4)
#define C3_SMEM ((23*(4*23*9)       + 32*292) * 4)
#define C4_SMEM ((13*(4*13*9)       + 32*292) * 4)

extern "C" void kernel_launch(void* const* d_in, const int* in_sizes, int n_in,
                              void* d_out, int out_size) {
    const float* inputs = (const float*)d_in[0];
    const float* rnn_in = (const float*)d_in[1];
    const float* mask   = (const float*)d_in[2];
    const int*   actions= (const int*)  d_in[3];
    const float* w1 = (const float*)d_in[4];  const float* b1 = (const float*)d_in[5];
    const float* w2 = (const float*)d_in[6];  const float* b2 = (const float*)d_in[7];
    const float* w3 = (const float*)d_in[8];  const float* b3 = (const float*)d_in[9];
    const float* w4 = (const float*)d_in[10]; const float* b4 = (const float*)d_in[11];
    const float* W_ih = (const float*)d_in[12];
    const float* W_hh = (const float*)d_in[13];
    const float* b_ih = (const float*)d_in[14];
    const float* b_hh = (const float*)d_in[15];
    const float* Wc = (const float*)d_in[16]; const float* bc = (const float*)d_in[17];
    const float* Wa = (const float*)d_in[18]; const float* ba = (const float*)d_in[19];
    float* out = (float*)d_out;

    float *a1, *a2, *a3, *xf, *gi, *outs;
    cudaGetSymbolAddress((void**)&a1, g_a1);
    cudaGetSymbolAddress((void**)&a2, g_a2);
    cudaGetSymbolAddress((void**)&a3, g_a3);
    cudaGetSymbolAddress((void**)&xf, g_xf);
    cudaGetSymbolAddress((void**)&gi, g_gi);
    cudaGetSymbolAddress((void**)&outs, g_outs);

    cudaFuncSetAttribute((conv_mma<4,84,42,6,true,false>),  cudaFuncAttributeMaxDynamicSharedMemorySize, C1_SMEM);
    cudaFuncSetAttribute((conv_mma<32,42,21,7,false,false>),cudaFuncAttributeMaxDynamicSharedMemorySize, C2_SMEM);
    cudaFuncSetAttribute((conv_mma<32,21,11,11,false,false>),cudaFuncAttributeMaxDynamicSharedMemorySize, C3_SMEM);
    cudaFuncSetAttribute((conv_mma<32,11,6,6,false,true>),  cudaFuncAttributeMaxDynamicSharedMemorySize, C4_SMEM);

    conv_mma<4,84,42,6,true,false>  <<<dim3(NTB,7), 256, C1_SMEM>>>(inputs, w1, b1, a1);
    conv_mma<32,42,21,7,false,false><<<dim3(NTB,3), 256, C2_SMEM>>>(a1, w2, b2, a2);
    conv_mma<32,21,11,11,false,false><<<dim3(NTB,1), 256, C3_SMEM>>>(a2, w3, b3, a3);
    conv_mma<32,11,6,6,false,true>  <<<dim3(NTB,1), 256, C4_SMEM>>>(a3, w4, b4, xf);

    gemm_tf32<<<dim3(768/64, 2048/64), 256>>>(xf, W_ih, b_ih, gi);

    gru_kernel<<<GRU_BLOCKS, GRU_THREADS>>>(rnn_in, mask, W_hh, b_hh, gi, outs, out + 8192);

    heads_kernel<<<256, 256>>>(outs, actions, Wc, bc, Wa, ba, out);
}

// round 3
// speedup vs baseline: 2.7646x; 1.5265x over previous
#include <cuda_runtime.h>
#include <cuda_fp16.h>
#include <cuda_bf16.h>
#include <cstdint>

// ---------------------------------------------------------------------------
// Problem constants
// ---------------------------------------------------------------------------
#define TT   64
#define BB   32
#define NTB  2048
#define HID  256
#define FEAT 1152

__device__ __half g_a1[2048u*32*42*42];   // NHWC f16
__device__ __half g_a2[2048u*32*21*21];   // NHWC f16
__device__ __half g_a3[2048u*32*11*11];   // NHWC f16
__device__ float  g_xf[2048u*1152];       // reference feature order
__device__ float  g_gi[2048u*768];
__device__ float  g_outs[2048u*256];
__device__ float  g_h[2][BB*HID];
__device__ unsigned g_bar_cnt = 0;
__device__ unsigned g_bar_phase = 0;

// ---------------------------------------------------------------------------
// tf32 helpers
// ---------------------------------------------------------------------------
__device__ __forceinline__ float tf32r(float f) {
    uint32_t u; asm("cvt.rna.tf32.f32 %0, %1;" : "=r"(u) : "f"(f));
    return __uint_as_float(u);
}
__device__ __forceinline__ void mma8(float4& d, float a0, float a1, float a2, float a3,
                                     float b0, float b1) {
    asm volatile("mma.sync.aligned.m16n8k8.row.col.f32.tf32.tf32.f32 "
        "{%0,%1,%2,%3},{%4,%5,%6,%7},{%8,%9},{%0,%1,%2,%3};"
        : "+f"(d.x), "+f"(d.y), "+f"(d.z), "+f"(d.w)
        : "r"(__float_as_uint(a0)), "r"(__float_as_uint(a1)),
          "r"(__float_as_uint(a2)), "r"(__float_as_uint(a3)),
          "r"(__float_as_uint(b0)), "r"(__float_as_uint(b1)));
}
__device__ __forceinline__ float eluf(float x) { return x > 0.f ? x : expm1f(x); }

// ---------------------------------------------------------------------------
// Implicit-GEMM conv3x3 stride2 pad1, OC=32, tf32 mma, fp16 NHWC intermediates.
// Block = (IMGS images, band of BAND output rows). 256 threads = 8 warps
//   = 2 (m16 halves of OC=32) x 4 (pixel-tile groups of 8 pixels).
// IC=32 path processes input channels in 16-ch chunks (halved smem).
// INMODE: 0 = fp32 NCHW (layer 1), 1 = f16 NHWC.
// OUTMODE: 0 = f16 NHWC, 1 = fp32 reference feature order (layer 4).
// ---------------------------------------------------------------------------
template<int IC, int IH, int OH, int BAND, int IMGS, int ICC, int INMODE, int OUTMODE>
__global__ void __launch_bounds__(256) conv_mma(const void* __restrict__ in_,
        const float* __restrict__ wgt, const float* __restrict__ bias,
        void* __restrict__ out_)
{
    constexpr int OW = OH, IW = IH;
    constexpr bool C1 = (IC == 4);
    constexpr int CH = IC / ICC;                 // k-chunks
    constexpr int G  = C1 ? 1 : ICC/8;           // 8-ch groups per chunk
    constexpr int KSC = C1 ? 6 : (ICC*9)/8;      // k8 steps per chunk
    constexpr int KW = C1 ? 48 : IC*9;
    constexpr int AS = KW + 4;
    constexpr int ROWS = 2*BAND + 1;
    constexpr int RW = C1 ? (IW+2)*4 : G*(IW+2)*9;
    constexpr int SIN_IMG = ROWS*RW;
    constexpr int SIN = IMGS*SIN_IMG;
    constexpr int NPIX = BAND*OW;
    constexpr int NPIXT = IMGS*NPIX;
    constexpr int NT8 = (NPIXT+7)/8;
    constexpr int NTW = (NT8+3)/4;
    constexpr int OHW = OH*OW;
    static_assert(C1 || G == 2, "IC32 path assumes 16-ch chunks");

    extern __shared__ float sm[];
    float* s_in = sm;
    float* s_w  = sm + SIN;

    const int tid = threadIdx.x;
    const int n0 = blockIdx.x * IMGS;
    const int oy0 = blockIdx.y * BAND;
    const int ybase = 2*oy0 - 1;

    for (int i = tid; i < SIN; i += 256) s_in[i] = 0.f;

    // ---- stage weights (k-major per oc, tf32) ----
    if (C1) {
        for (int i = tid; i < 32*48; i += 256) {
            int oc = i/48, r = i - oc*48;
            int ky = r>>4, rr = r&15, kx = rr>>2, ic = rr&3;
            float v = (kx < 3) ? wgt[((oc*4+ic)*3+ky)*3+kx] : 0.f;
            s_w[oc*AS + r] = tf32r(v);
        }
    } else {
        for (int i = tid; i < 32*288; i += 256) {
            int oc = i/288, r = i - oc*288;
            int s = r>>3, ii = r&7;
            int tap = s>>2, g = s&3, ic = g*8+ii, ky = tap/3, kx = tap - ky*3;
            s_w[oc*AS + r] = tf32r(wgt[((oc*IC+ic)*3+ky)*3+kx]);
        }
    }
    __syncthreads();

    const int lane = tid & 31, warp = tid >> 5;
    const int m0 = (warp & 1)*16;
    const int ng = warp >> 1;
    const int gq = lane >> 2, tq = lane & 3;

    int pixbase[NTW];
    #pragma unroll
    for (int j = 0; j < NTW; j++) {
        int tile = ng + 4*j;
        int p = tile*8 + gq;
        int pp = (p < NPIXT) ? p : 0;
        int img, rp;
        if (IMGS == 1) { img = 0; rp = pp; } else { img = pp / NPIX; rp = pp - img*NPIX; }
        int dy = rp / OW, ox = rp - dy*OW;
        pixbase[j] = img*SIN_IMG + (C1 ? (2*dy*RW + 8*ox + tq) : (2*dy*RW + 18*ox + tq));
    }

    float4 acc[NTW];
    #pragma unroll
    for (int j = 0; j < NTW; j++) acc[j] = make_float4(0.f,0.f,0.f,0.f);

    const int y_lo = (ybase < 0) ? 0 : ybase;
    int y_hi = ybase + ROWS - 1; if (y_hi > IH-1) y_hi = IH-1;
    const int nrows = y_hi - y_lo + 1;
    const float* swr = s_w + (m0 + gq)*AS + tq;

    #pragma unroll
    for (int ch = 0; ch < CH; ch++) {
        if (CH > 1 && ch) __syncthreads();
        // ---- stage input chunk ----
        if (INMODE == 0) {
            const float* inF = (const float*)in_;
            for (int i = tid; i < nrows*IW; i += 256) {
                int x = i % IW; int yy = i / IW; int y = y_lo + yy;
                const float* bsrc = inF + (((size_t)n0*IC)*IH + y)*IW + x;
                float* drow = s_in + (y - ybase)*RW + (x+1)*4;
                #pragma unroll
                for (int c = 0; c < 4; c++) drow[c] = tf32r(bsrc[(size_t)c*IH*IW]);
            }
        } else {
            const __half* inH = (const __half*)in_;
            const int c0 = ch*ICC;
            for (int i = tid; i < IMGS*nrows*IW*2; i += 256) {
                int g = i & 1;
                int q = i >> 1;
                int x = q % IW; int t3 = q / IW;
                int yy, img;
                if (IMGS == 1) { yy = t3; img = 0; } else { yy = t3 % nrows; img = t3 / nrows; }
                int y = y_lo + yy;
                const __half* src = inH + (((size_t)(n0+img)*IH + y)*IW + x)*IC + c0 + g*8;
                uint4 raw = *(const uint4*)src;
                float* d = s_in + img*SIN_IMG + (y - ybase)*RW + (g*(IW+2) + x + 1)*9;
                float2 f0 = __half22float2(*(__half2*)&raw.x);
                float2 f1 = __half22float2(*(__half2*)&raw.y);
                float2 f2 = __half22float2(*(__half2*)&raw.z);
                float2 f3 = __half22float2(*(__half2*)&raw.w);
                d[0]=f0.x; d[1]=f0.y; d[2]=f1.x; d[3]=f1.y;
                d[4]=f2.x; d[5]=f2.y; d[6]=f3.x; d[7]=f3.y;
            }
        }
        __syncthreads();
        // ---- mma over this chunk's k-steps ----
        #pragma unroll
        for (int sc = 0; sc < KSC; sc++) {
            int sg, uoff;
            if (C1) {
                sg = sc; int ky = sc>>1, h = sc&1; uoff = ky*RW + h*8;
            } else {
                int tap = sc>>1, gl = sc&1;
                sg = tap*4 + ch*2 + gl;
                int ky = tap/3, kx = tap - ky*3;
                uoff = ky*RW + (gl*(IW+2)+kx)*9;
            }
            float a0 = swr[sg*8];
            float a1 = swr[sg*8 + 8*AS];
            float a2 = swr[sg*8 + 4];
            float a3 = swr[sg*8 + 8*AS + 4];
            #pragma unroll
            for (int j = 0; j < NTW; j++) {
                const float* bp = s_in + pixbase[j] + uoff;
                mma8(acc[j], a0, a1, a2, a3, bp[0], bp[4]);
            }
        }
    }

    // ---- epilogue ----
    const int oc = m0 + gq;
    const float b0v = __ldg(&bias[oc]);
    const float b8v = __ldg(&bias[oc+8]);

    auto store_px = [&](int p, int occ, float v) {
        if (p >= NPIXT) return;
        int img, lp;
        if (IMGS == 1) { img = 0; lp = p; } else { img = p / NPIX; lp = p - img*NPIX; }
        if (OUTMODE == 1) {
            float* ob = (float*)out_ + (size_t)(n0+img)*1152;
            ob[occ*36 + lp] = v;
        } else {
            __half* ob = (__half*)out_ + ((size_t)(n0+img)*OHW + oy0*OW + lp)*32;
            ob[occ] = __float2half_rn(v);
        }
    };

    #pragma unroll
    for (int j = 0; j < NTW; j++) {
        int tile = ng + 4*j;
        if (tile >= NT8) continue;
        int pc = tile*8 + tq*2;
        store_px(pc,   oc,   eluf(acc[j].x + b0v));
        store_px(pc+1, oc,   eluf(acc[j].y + b0v));
        store_px(pc,   oc+8, eluf(acc[j].z + b8v));
        store_px(pc+1, oc+8, eluf(acc[j].w + b8v));
    }
}

// ---------------------------------------------------------------------------
// gi[2048,768] = xf[2048,1152] @ W_ih[768,1152]^T + b_ih    (tf32 mma)
// ---------------------------------------------------------------------------
__global__ void __launch_bounds__(256) gemm_tf32(const float* __restrict__ A,
        const float* __restrict__ B, const float* __restrict__ bias,
        float* __restrict__ C)
{
    constexpr int KCP = 20;
    __shared__ float As[64*KCP], Bs[64*KCP];
    const int bm = blockIdx.y*64, bn = blockIdx.x*64;
    const int tid = threadIdx.x, lane = tid&31, warp = tid>>5;
    const int wm = (warp&1)*32, wn = (warp>>1)*16;
    const int gq = lane>>2, tq = lane&3;
    const int ldr = tid>>2, ldk = (tid&3)*4;

    float4 acc[2][2];
    #pragma unroll
    for (int i = 0; i < 2; i++)
        #pragma unroll
        for (int j = 0; j < 2; j++) acc[i][j] = make_float4(0.f,0.f,0.f,0.f);

    for (int k0 = 0; k0 < FEAT; k0 += 16) {
        float4 av = *(const float4*)(A + (size_t)(bm+ldr)*FEAT + k0 + ldk);
        float4 bv = *(const float4*)(B + (size_t)(bn+ldr)*FEAT + k0 + ldk);
        av.x = tf32r(av.x); av.y = tf32r(av.y); av.z = tf32r(av.z); av.w = tf32r(av.w);
        bv.x = tf32r(bv.x); bv.y = tf32r(bv.y); bv.z = tf32r(bv.z); bv.w = tf32r(bv.w);
        *(float4*)(As + ldr*KCP + ldk) = av;
        *(float4*)(Bs + ldr*KCP + ldk) = bv;
        __syncthreads();
        #pragma unroll
        for (int ks = 0; ks < 2; ks++) {
            #pragma unroll
            for (int mi = 0; mi < 2; mi++) {
                const float* ap = As + (wm + mi*16 + gq)*KCP + ks*8 + tq;
                float a0 = ap[0], a1 = ap[8*KCP], a2 = ap[4], a3 = ap[8*KCP+4];
                #pragma unroll
                for (int ni = 0; ni < 2; ni++) {
                    const float* bp = Bs + (wn + ni*8 + gq)*KCP + ks*8 + tq;
                    mma8(acc[mi][ni], a0, a1, a2, a3, bp[0], bp[4]);
                }
            }
        }
        __syncthreads();
    }
    #pragma unroll
    for (int mi = 0; mi < 2; mi++) {
        #pragma unroll
        for (int ni = 0; ni < 2; ni++) {
            int row = bm + wm + mi*16 + gq;
            int col = bn + wn + ni*8 + tq*2;
            float bb0 = __ldg(&bias[col]), bb1 = __ldg(&bias[col+1]);
            C[(size_t)row*768 + col]       = acc[mi][ni].x + bb0;
            C[(size_t)row*768 + col + 1]   = acc[mi][ni].y + bb1;
            C[(size_t)(row+8)*768 + col]   = acc[mi][ni].z + bb0;
            C[(size_t)(row+8)*768 + col+1] = acc[mi][ni].w + bb1;
        }
    }
}

// ---------------------------------------------------------------------------
// Persistent GRU
// ---------------------------------------------------------------------------
#define GRU_BLOCKS 64
#define GRU_THREADS 384

__device__ __forceinline__ void grid_barrier(unsigned target) {
    __threadfence();
    __syncthreads();
    if (threadIdx.x == 0) {
        unsigned v = atomicAdd(&g_bar_cnt, 1);
        if (v == GRU_BLOCKS - 1) {
            g_bar_cnt = 0;
            __threadfence();
            atomicAdd(&g_bar_phase, 1);
        } else {
            while ((int)(*(volatile unsigned*)&g_bar_phase - target) < 0) { __nanosleep(32); }
        }
        __threadfence();
    }
    __syncthreads();
}

__global__ void gru_kernel(const float* __restrict__ rnn_in, const float* __restrict__ mask,
                           const float* __restrict__ W_hh, const float* __restrict__ b_hh,
                           const float* __restrict__ gi_all, float* __restrict__ outs,
                           float* __restrict__ hfin) {
    __shared__ float s_w[12*256];
    __shared__ float s_h[BB*HID];
    __shared__ float s_gh[384];
    __shared__ float s_bhh[12];

    const int tid = threadIdx.x;
    const int bx  = blockIdx.x;

    for (int i = tid; i < 12*256; i += GRU_THREADS) {
        int rl = i >> 8, k = i & 255;
        int gate = rl >> 2, gj = rl & 3;
        s_w[i] = W_hh[(size_t)(gate*256 + bx*4 + gj)*256 + k];
    }
    if (tid < 12) {
        int gate = tid >> 2, gj = tid & 3;
        s_bhh[tid] = b_hh[gate*256 + bx*4 + gj];
    }
    if (bx == 0) {
        for (int i = tid; i < BB*HID; i += GRU_THREADS) g_h[0][i] = rnn_in[i];
    }
    unsigned tgt = *(volatile unsigned*)&g_bar_phase;
    grid_barrier(++tgt);

    for (int t = 0; t < TT; t++) {
        const float* hprev = g_h[t & 1];
        for (int i = tid; i < BB*HID; i += GRU_THREADS) {
            int b = i >> 8, k = i & 255;
            s_h[k*32 + b] = __ldcg(&hprev[i]) * __ldg(&mask[t*32 + b]);
        }
        __syncthreads();
        {
            int gate = tid / 128;
            int r    = tid - gate*128;
            int gj   = r >> 5, b = r & 31;
            int rl   = gate*4 + gj;
            const float* wrow = s_w + rl*256;
            float acc = s_bhh[rl];
            #pragma unroll 8
            for (int k = 0; k < 256; k++) acc += s_h[k*32 + b] * wrow[k];
            s_gh[tid] = acc;
        }
        __syncthreads();
        if (tid < 128) {
            int gj = tid >> 5, b = tid & 31;
            int g  = bx*4 + gj;
            const float* gi = gi_all + (size_t)(t*32 + b)*768;
            float ghr = s_gh[0*128 + gj*32 + b];
            float ghz = s_gh[1*128 + gj*32 + b];
            float ghn = s_gh[2*128 + gj*32 + b];
            float rr = 1.f / (1.f + expf(-(__ldg(&gi[g])       + ghr)));
            float zz = 1.f / (1.f + expf(-(__ldg(&gi[256 + g]) + ghz)));
            float nn = tanhf(__ldg(&gi[512 + g]) + rr*ghn);
            float hold = s_h[g*32 + b];
            float hn = (1.f - zz)*nn + zz*hold;
            g_h[(t + 1) & 1][b*256 + g] = hn;
            outs[(size_t)(t*32 + b)*256 + g] = hn;
            if (t == TT - 1) hfin[b*256 + g] = hn;
        }
        grid_barrier(++tgt);
    }
}

// ---------------------------------------------------------------------------
// Heads
// ---------------------------------------------------------------------------
__global__ void heads_kernel(const float* __restrict__ outs, const int* __restrict__ actions,
                             const float* __restrict__ Wc, const float* __restrict__ bc,
                             const float* __restrict__ Wa, const float* __restrict__ ba,
                             float* __restrict__ d_out) {
    int warp = (blockIdx.x * blockDim.x + threadIdx.x) >> 5;
    int lane = threadIdx.x & 31;
    if (warp >= NTB) return;
    const float* o = outs + (size_t)warp * 256;

    float acc[13];
    #pragma unroll
    for (int g = 0; g < 13; g++) acc[g] = 0.f;
    #pragma unroll
    for (int i = 0; i < 8; i++) {
        int k = lane + 32*i;
        float x = o[k];
        acc[0] += x * __ldg(&Wc[k]);
        #pragma unroll
        for (int g = 0; g < 12; g++) acc[1 + g] += x * __ldg(&Wa[g*256 + k]);
    }
    #pragma unroll
    for (int g = 0; g < 13; g++) {
        #pragma unroll
        for (int s = 16; s > 0; s >>= 1) acc[g] += __shfl_xor_sync(0xFFFFFFFFu, acc[g], s);
    }
    if (lane == 0) {
        float v = acc[0] + bc[0];
        float l[12];
        float m = -1e30f;
        #pragma unroll
        for (int g = 0; g < 12; g++) { l[g] = acc[1 + g] + ba[g]; m = fmaxf(m, l[g]); }
        float s = 0.f, sl = 0.f;
        #pragma unroll
        for (int g = 0; g < 12; g++) {
            float e = expf(l[g] - m);
            s += e; sl += e * l[g];
        }
        float logZ = m + logf(s);
        int a = actions[warp];
        d_out[warp]        = v;
        d_out[2048 + warp] = (float)a;
        d_out[4096 + warp] = l[a] - logZ;
        d_out[6144 + warp] = logZ - sl / s;
    }
}

// ---------------------------------------------------------------------------
// Host launcher
// ---------------------------------------------------------------------------
#define C1_SMEM ((13*344          + 32*52 ) * 4)   // 24,544
#define C2_SMEM ((15*792          + 32*292) * 4)   // 84,896
#define C3_SMEM ((23*414          + 32*292) * 4)   // 75,464
#define C4_SMEM ((2*13*234        + 32*292) * 4)   // 61,712

extern "C" void kernel_launch(void* const* d_in, const int* in_sizes, int n_in,
                              void* d_out, int out_size) {
    const float* inputs = (const float*)d_in[0];
    const float* rnn_in = (const float*)d_in[1];
    const float* mask   = (const float*)d_in[2];
    const int*   actions= (const int*)  d_in[3];
    const float* w1 = (const float*)d_in[4];  const float* b1 = (const float*)d_in[5];
    const float* w2 = (const float*)d_in[6];  const float* b2 = (const float*)d_in[7];
    const float* w3 = (const float*)d_in[8];  const float* b3 = (const float*)d_in[9];
    const float* w4 = (const float*)d_in[10]; const float* b4 = (const float*)d_in[11];
    const float* W_ih = (const float*)d_in[12];
    const float* W_hh = (const float*)d_in[13];
    const float* b_ih = (const float*)d_in[14];
    const float* b_hh = (const float*)d_in[15];
    const float* Wc = (const float*)d_in[16]; const float* bc = (const float*)d_in[17];
    const float* Wa = (const float*)d_in[18]; const float* ba = (const float*)d_in[19];
    float* out = (float*)d_out;

    __half *a1, *a2, *a3;
    float *xf, *gi, *outs;
    cudaGetSymbolAddress((void**)&a1, g_a1);
    cudaGetSymbolAddress((void**)&a2, g_a2);
    cudaGetSymbolAddress((void**)&a3, g_a3);
    cudaGetSymbolAddress((void**)&xf, g_xf);
    cudaGetSymbolAddress((void**)&gi, g_gi);
    cudaGetSymbolAddress((void**)&outs, g_outs);

    cudaFuncSetAttribute((conv_mma<4,84,42,6,1,4,0,0>),    cudaFuncAttributeMaxDynamicSharedMemorySize, C1_SMEM);
    cudaFuncSetAttribute((conv_mma<32,42,21,7,1,16,1,0>),  cudaFuncAttributeMaxDynamicSharedMemorySize, C2_SMEM);
    cudaFuncSetAttribute((conv_mma<32,21,11,11,1,16,1,0>), cudaFuncAttributeMaxDynamicSharedMemorySize, C3_SMEM);
    cudaFuncSetAttribute((conv_mma<32,11,6,6,2,16,1,1>),   cudaFuncAttributeMaxDynamicSharedMemorySize, C4_SMEM);

    conv_mma<4,84,42,6,1,4,0,0>    <<<dim3(NTB,7), 256, C1_SMEM>>>(inputs, w1, b1, a1);
    conv_mma<32,42,21,7,1,16,1,0>  <<<dim3(NTB,3), 256, C2_SMEM>>>(a1, w2, b2, a2);
    conv_mma<32,21,11,11,1,16,1,0> <<<dim3(NTB,1), 256, C3_SMEM>>>(a2, w3, b3, a3);
    conv_mma<32,11,6,6,2,16,1,1>   <<<dim3(NTB/2,1), 256, C4_SMEM>>>(a3, w4, b4, xf);

    gemm_tf32<<<dim3(768/64, 2048/64), 256>>>(xf, W_ih, b_ih, gi);

    gru_kernel<<<GRU_BLOCKS, GRU_THREADS>>>(rnn_in, mask, W_hh, b_hh, gi, outs, out + 8192);

    heads_kernel<<<256, 256>>>(outs, actions, Wc, bc, Wa, ba, out);
}

// round 4
// speedup vs baseline: 4.2717x; 1.5451x over previous
#include <cuda_runtime.h>
#include <cuda_fp16.h>
#include <cstdint>

// ---------------------------------------------------------------------------
#define TT   64
#define BB   32
#define NTB  2048
#define HID  256
#define FEAT 1152

__device__ __half g_a1[2048u*32*42*42];   // NHWC f16
__device__ __half g_a2[2048u*32*21*21];   // NHWC f16
__device__ __half g_a3[2048u*32*11*11];   // NHWC f16
__device__ __half g_xf[2048u*1152];       // f16, reference feature order
__device__ float  g_gi[2048u*768];
__device__ float  g_outs[2048u*256];
__device__ float  g_h[2][BB*HID];
__device__ unsigned g_bar_cnt = 0;
__device__ unsigned g_bar_phase = 0;

// ---------------------------------------------------------------------------
__device__ __forceinline__ void mma16(float4& d, uint32_t a0, uint32_t a1,
                                      uint32_t a2, uint32_t a3,
                                      uint32_t b0, uint32_t b1) {
    asm volatile("mma.sync.aligned.m16n8k16.row.col.f32.f16.f16.f32 "
        "{%0,%1,%2,%3},{%4,%5,%6,%7},{%8,%9},{%0,%1,%2,%3};"
        : "+f"(d.x), "+f"(d.y), "+f"(d.z), "+f"(d.w)
        : "r"(a0), "r"(a1), "r"(a2), "r"(a3), "r"(b0), "r"(b1));
}
__device__ __forceinline__ float eluf(float x) { return x > 0.f ? x : expm1f(x); }

// ---------------------------------------------------------------------------
// fp16 implicit-GEMM conv3x3 stride2 pad1, OC=32, m16n8k16.
// IC=4 (layer1): per x-position 4 halves [x][c]; one k16 step per ky (kx-pad col 3 zero-weighted).
// IC=32: per x-position 40-half slot (32 data + 8 pad -> conflict-free stride);
//        k16 step = (tap, 16-ch half). 18 steps.
// INMODE: 0 = fp32 NCHW input, 1 = f16 NHWC. OUTMODE: 0 = f16 NHWC, 1 = f16 ref-order (xf).
// ---------------------------------------------------------------------------
template<int IC, int IH, int OH, int BAND, int IMGS, int INMODE, int OUTMODE>
__global__ void __launch_bounds__(256) conv_f16(const void* __restrict__ in_,
        const float* __restrict__ wgt, const float* __restrict__ bias,
        void* __restrict__ out_)
{
    constexpr int OW = OH, IW = IH;
    constexpr bool C1 = (IC == 4);
    constexpr int XS = C1 ? 4 : 40;            // halves per x slot
    constexpr int RW = (IW+2)*XS;              // halves per input row
    constexpr int ROWS = 2*BAND + 1;
    constexpr int SIN_IMG = ROWS*RW;
    constexpr int SIN = IMGS*SIN_IMG;
    constexpr int KS = C1 ? 3 : 18;            // k16 steps
    constexpr int APAD = C1 ? 56 : 296;        // halves per oc weight row
    constexpr int NPIX = BAND*OW;
    constexpr int NPIXT = IMGS*NPIX;
    constexpr int NT8 = (NPIXT+7)/8;
    constexpr int NTW = (NT8+3)/4;
    constexpr int OHW = OH*OW;

    extern __shared__ __half sh[];
    __half* s_in = sh;
    __half* s_w  = sh + SIN;

    const int tid = threadIdx.x;
    const int n0 = blockIdx.x * IMGS;
    const int oy0 = blockIdx.y * BAND;
    const int ybase = 2*oy0 - 1;

    for (int i = tid; i < SIN/8; i += 256) ((uint4*)s_in)[i] = make_uint4(0,0,0,0);

    // ---- weights: k-major f16 per oc ----
    if (C1) {
        for (int i = tid; i < 32*48; i += 256) {
            int oc = i/48, r = i - oc*48;
            int ky = r>>4, rr = r&15, kx = rr>>2, ic = rr&3;
            float v = (kx < 3) ? wgt[((oc*4+ic)*3+ky)*3+kx] : 0.f;
            s_w[oc*APAD + r] = __float2half_rn(v);
        }
    } else {
        for (int i = tid; i < 32*288; i += 256) {
            int oc = i/288, r = i - oc*288;
            int s = r>>4, c = r&15;
            int tap = s>>1, ch = s&1;
            int ky = tap/3, kx = tap - ky*3;
            s_w[oc*APAD + r] = __float2half_rn(wgt[((oc*32 + ch*16 + c)*3+ky)*3+kx]);
        }
    }

    const int y_lo = (ybase < 0) ? 0 : ybase;
    int y_hi = ybase + ROWS - 1; if (y_hi > IH-1) y_hi = IH-1;
    const int nrows = y_hi - y_lo + 1;

    // ---- input staging ----
    if (INMODE == 0) {
        const float* inF = (const float*)in_;
        for (int i = tid; i < nrows*IW; i += 256) {
            int x = i % IW; int yy = i / IW; int y = y_lo + yy;
            const float* p = inF + (((size_t)n0*4)*IH + y)*IW + x;
            __half2 h01 = __floats2half2_rn(p[0], p[(size_t)IH*IW]);
            __half2 h23 = __floats2half2_rn(p[2*(size_t)IH*IW], p[3*(size_t)IH*IW]);
            __half* d = s_in + (y - ybase)*RW + (x+1)*4;
            *(__half2*)d = h01; *(__half2*)(d+2) = h23;
        }
    } else {
        const __half* inH = (const __half*)in_;
        for (int i = tid; i < IMGS*nrows*IW*4; i += 256) {
            int g = i & 3, q = i >> 2;
            int x = q % IW; int t3 = q / IW;
            int yy, img;
            if (IMGS == 1) { yy = t3; img = 0; } else { yy = t3 % nrows; img = t3 / nrows; }
            int y = y_lo + yy;
            uint4 v = *(const uint4*)(inH + (((size_t)(n0+img)*IH + y)*IW + x)*32 + g*8);
            *(uint4*)(s_in + img*SIN_IMG + (y - ybase)*RW + (x+1)*40 + g*8) = v;
        }
    }
    __syncthreads();

    const int lane = tid & 31, warp = tid >> 5;
    const int m0 = (warp & 1)*16;
    const int ng = warp >> 1;
    const int gq = lane >> 2, tq = lane & 3;

    int pixbase[NTW];
    #pragma unroll
    for (int j = 0; j < NTW; j++) {
        int tile = ng + 4*j;
        int p = tile*8 + gq;
        int pp = (p < NPIXT) ? p : 0;
        int img, rp;
        if (IMGS == 1) { img = 0; rp = pp; } else { img = pp / NPIX; rp = pp - img*NPIX; }
        int dy = rp / OW, ox = rp - dy*OW;
        pixbase[j] = img*SIN_IMG + 2*dy*RW + 2*ox*XS + 2*tq;
    }

    float4 acc[NTW];
    #pragma unroll
    for (int j = 0; j < NTW; j++) acc[j] = make_float4(0.f,0.f,0.f,0.f);

    const __half* swr = s_w + (m0 + gq)*APAD + 2*tq;
    #pragma unroll
    for (int s = 0; s < KS; s++) {
        uint32_t a0 = *(const uint32_t*)(swr + s*16);
        uint32_t a1 = *(const uint32_t*)(swr + s*16 + 8*APAD);
        uint32_t a2 = *(const uint32_t*)(swr + s*16 + 8);
        uint32_t a3 = *(const uint32_t*)(swr + s*16 + 8*APAD + 8);
        int off;
        if (C1) { off = s*RW; }
        else { int tap = s>>1, ch = s&1; int ky = tap/3, kx = tap - ky*3;
               off = ky*RW + kx*40 + ch*16; }
        #pragma unroll
        for (int j = 0; j < NTW; j++) {
            const __half* bp = s_in + pixbase[j] + off;
            mma16(acc[j], a0, a1, a2, a3,
                  *(const uint32_t*)bp, *(const uint32_t*)(bp + 8));
        }
    }

    // ---- epilogue ----
    const int oc = m0 + gq;
    const float b0v = __ldg(&bias[oc]);
    const float b8v = __ldg(&bias[oc+8]);

    auto store_px = [&](int p, int occ, float v) {
        if (p >= NPIXT) return;
        int img, lp;
        if (IMGS == 1) { img = 0; lp = p; } else { img = p / NPIX; lp = p - img*NPIX; }
        if (OUTMODE == 1) {
            __half* ob = (__half*)out_ + (size_t)(n0+img)*1152;
            ob[occ*36 + lp] = __float2half_rn(v);
        } else {
            __half* ob = (__half*)out_ + ((size_t)(n0+img)*OHW + oy0*OW + lp)*32;
            ob[occ] = __float2half_rn(v);
        }
    };

    #pragma unroll
    for (int j = 0; j < NTW; j++) {
        int tile = ng + 4*j;
        if (tile >= NT8) continue;
        int pc = tile*8 + tq*2;
        store_px(pc,   oc,   eluf(acc[j].x + b0v));
        store_px(pc+1, oc,   eluf(acc[j].y + b0v));
        store_px(pc,   oc+8, eluf(acc[j].z + b8v));
        store_px(pc+1, oc+8, eluf(acc[j].w + b8v));
    }
}

// ---------------------------------------------------------------------------
// gi[2048,768] = xf[2048,1152](f16) @ W_ih[768,1152]^T + b_ih    (f16 mma, f32 acc)
// 64x64 tile, k-chunk 32, 8 warps = 2m x 4n, warp tile 32x16.
// ---------------------------------------------------------------------------
__global__ void __launch_bounds__(256) gemm_f16(const __half* __restrict__ A,
        const float* __restrict__ B, const float* __restrict__ bias,
        float* __restrict__ C)
{
    constexpr int ST = 40;   // half stride per row (32 + 8 pad)
    __shared__ __half As[64*ST], Bs[64*ST];
    const int bm = blockIdx.y*64, bn = blockIdx.x*64;
    const int tid = threadIdx.x, lane = tid&31, warp = tid>>5;
    const int wm = (warp&1)*32, wn = (warp>>1)*16;
    const int gq = lane>>2, tq = lane&3;
    const int ldr = tid>>2, ldk = (tid&3)*8;

    float4 acc[2][2];
    #pragma unroll
    for (int i = 0; i < 2; i++)
        #pragma unroll
        for (int j = 0; j < 2; j++) acc[i][j] = make_float4(0.f,0.f,0.f,0.f);

    for (int k0 = 0; k0 < FEAT; k0 += 32) {
        uint4 av = *(const uint4*)(A + (size_t)(bm+ldr)*FEAT + k0 + ldk);
        *(uint4*)(As + ldr*ST + ldk) = av;
        float4 f0 = *(const float4*)(B + (size_t)(bn+ldr)*FEAT + k0 + ldk);
        float4 f1 = *(const float4*)(B + (size_t)(bn+ldr)*FEAT + k0 + ldk + 4);
        __half2 p0 = __floats2half2_rn(f0.x, f0.y);
        __half2 p1 = __floats2half2_rn(f0.z, f0.w);
        __half2 p2 = __floats2half2_rn(f1.x, f1.y);
        __half2 p3 = __floats2half2_rn(f1.z, f1.w);
        uint4 bvv;
        bvv.x = *(uint32_t*)&p0; bvv.y = *(uint32_t*)&p1;
        bvv.z = *(uint32_t*)&p2; bvv.w = *(uint32_t*)&p3;
        *(uint4*)(Bs + ldr*ST + ldk) = bvv;
        __syncthreads();
        #pragma unroll
        for (int s = 0; s < 2; s++) {
            #pragma unroll
            for (int mi = 0; mi < 2; mi++) {
                const __half* ap = As + (wm + mi*16 + gq)*ST + s*16 + 2*tq;
                uint32_t a0 = *(const uint32_t*)ap;
                uint32_t a1 = *(const uint32_t*)(ap + 8*ST);
                uint32_t a2 = *(const uint32_t*)(ap + 8);
                uint32_t a3 = *(const uint32_t*)(ap + 8*ST + 8);
                #pragma unroll
                for (int ni = 0; ni < 2; ni++) {
                    const __half* bp = Bs + (wn + ni*8 + gq)*ST + s*16 + 2*tq;
                    mma16(acc[mi][ni], a0, a1, a2, a3,
                          *(const uint32_t*)bp, *(const uint32_t*)(bp + 8));
                }
            }
        }
        __syncthreads();
    }
    #pragma unroll
    for (int mi = 0; mi < 2; mi++) {
        #pragma unroll
        for (int ni = 0; ni < 2; ni++) {
            int row = bm + wm + mi*16 + gq;
            int col = bn + wn + ni*8 + tq*2;
            float bb0 = __ldg(&bias[col]), bb1 = __ldg(&bias[col+1]);
            C[(size_t)row*768 + col]       = acc[mi][ni].x + bb0;
            C[(size_t)row*768 + col + 1]   = acc[mi][ni].y + bb1;
            C[(size_t)(row+8)*768 + col]   = acc[mi][ni].z + bb0;
            C[(size_t)(row+8)*768 + col+1] = acc[mi][ni].w + bb1;
        }
    }
}

// ---------------------------------------------------------------------------
// Persistent GRU: 64 blocks x 128 threads. Thread (gj,b) computes ALL 3 gates
// for output column g = bx*4+gj, batch b: h-row read once per 3 dot products,
// float4 vectorized (h conflict-free via 260-stride, w rows broadcast).
// ---------------------------------------------------------------------------
#define GRU_BLOCKS 64
#define GRU_THREADS 128

__device__ __forceinline__ void grid_barrier(unsigned target) {
    __threadfence();
    __syncthreads();
    if (threadIdx.x == 0) {
        unsigned v = atomicAdd(&g_bar_cnt, 1);
        if (v == GRU_BLOCKS - 1) {
            g_bar_cnt = 0;
            __threadfence();
            atomicAdd(&g_bar_phase, 1);
        } else {
            while ((int)(*(volatile unsigned*)&g_bar_phase - target) < 0) { __nanosleep(32); }
        }
        __threadfence();
    }
    __syncthreads();
}

__global__ void gru_kernel(const float* __restrict__ rnn_in, const float* __restrict__ mask,
                           const float* __restrict__ W_hh, const float* __restrict__ b_hh,
                           const float* __restrict__ gi_all, float* __restrict__ outs,
                           float* __restrict__ hfin) {
    __shared__ float s_w[12*260];
    __shared__ float s_h[32*260];

    const int tid = threadIdx.x;
    const int bx  = blockIdx.x;

    for (int i = tid; i < 12*64; i += GRU_THREADS) {
        int rl = i >> 6, kq = i & 63;
        int gate = rl >> 2, gj2 = rl & 3;
        float4 w = *(const float4*)&W_hh[(size_t)(gate*256 + bx*4 + gj2)*256 + kq*4];
        *(float4*)&s_w[rl*260 + kq*4] = w;
    }
    if (bx == 0) {
        for (int i = tid; i < BB*HID; i += GRU_THREADS) g_h[0][i] = rnn_in[i];
    }
    unsigned tgt = *(volatile unsigned*)&g_bar_phase;
    grid_barrier(++tgt);

    const int gj = tid >> 5, b = tid & 31;
    const int g = bx*4 + gj;
    const float br = __ldg(&b_hh[g]);
    const float bz = __ldg(&b_hh[256 + g]);
    const float bn = __ldg(&b_hh[512 + g]);

    for (int t = 0; t < TT; t++) {
        const float* hprev = g_h[t & 1];
        for (int i = tid; i < 32*64; i += GRU_THREADS) {
            int bb = i >> 6, kq = i & 63;
            float m = __ldg(&mask[t*32 + bb]);
            float4 hv = __ldcg((const float4*)&hprev[bb*256 + kq*4]);
            hv.x *= m; hv.y *= m; hv.z *= m; hv.w *= m;
            *(float4*)&s_h[bb*260 + kq*4] = hv;
        }
        __syncthreads();
        float4 ar = make_float4(0.f,0.f,0.f,0.f), az = ar, an = ar;
        const float4* h4  = (const float4*)&s_h[b*260];
        const float4* wr4 = (const float4*)&s_w[(0 + gj)*260];
        const float4* wz4 = (const float4*)&s_w[(4 + gj)*260];
        const float4* wn4 = (const float4*)&s_w[(8 + gj)*260];
        #pragma unroll 8
        for (int kq = 0; kq < 64; kq++) {
            float4 h = h4[kq];
            float4 wr = wr4[kq], wz = wz4[kq], wn = wn4[kq];
            ar.x += h.x*wr.x; ar.y += h.y*wr.y; ar.z += h.z*wr.z; ar.w += h.w*wr.w;
            az.x += h.x*wz.x; az.y += h.y*wz.y; az.z += h.z*wz.z; az.w += h.w*wz.w;
            an.x += h.x*wn.x; an.y += h.y*wn.y; an.z += h.z*wn.z; an.w += h.w*wn.w;
        }
        float ghr = ar.x + ar.y + ar.z + ar.w + br;
        float ghz = az.x + az.y + az.z + az.w + bz;
        float ghn = an.x + an.y + an.z + an.w + bn;
        const float* gi = gi_all + (size_t)(t*32 + b)*768;
        float rr = 1.f / (1.f + expf(-(__ldg(&gi[g])       + ghr)));
        float zz = 1.f / (1.f + expf(-(__ldg(&gi[256 + g]) + ghz)));
        float nn = tanhf(__ldg(&gi[512 + g]) + rr*ghn);
        float hold = s_h[b*260 + g];
        float hn = (1.f - zz)*nn + zz*hold;
        g_h[(t + 1) & 1][b*256 + g] = hn;
        outs[(size_t)(t*32 + b)*256 + g] = hn;
        if (t == TT - 1) hfin[b*256 + g] = hn;
        grid_barrier(++tgt);
    }
}

// ---------------------------------------------------------------------------
// Heads
// ---------------------------------------------------------------------------
__global__ void heads_kernel(const float* __restrict__ outs, const int* __restrict__ actions,
                             const float* __restrict__ Wc, const float* __restrict__ bc,
                             const float* __restrict__ Wa, const float* __restrict__ ba,
                             float* __restrict__ d_out) {
    int warp = (blockIdx.x * blockDim.x + threadIdx.x) >> 5;
    int lane = threadIdx.x & 31;
    if (warp >= NTB) return;
    const float* o = outs + (size_t)warp * 256;

    float acc[13];
    #pragma unroll
    for (int g = 0; g < 13; g++) acc[g] = 0.f;
    #pragma unroll
    for (int i = 0; i < 8; i++) {
        int k = lane + 32*i;
        float x = o[k];
        acc[0] += x * __ldg(&Wc[k]);
        #pragma unroll
        for (int g = 0; g < 12; g++) acc[1 + g] += x * __ldg(&Wa[g*256 + k]);
    }
    #pragma unroll
    for (int g = 0; g < 13; g++) {
        #pragma unroll
        for (int s = 16; s > 0; s >>= 1) acc[g] += __shfl_xor_sync(0xFFFFFFFFu, acc[g], s);
    }
    if (lane == 0) {
        float v = acc[0] + bc[0];
        float l[12];
        float m = -1e30f;
        #pragma unroll
        for (int g = 0; g < 12; g++) { l[g] = acc[1 + g] + ba[g]; m = fmaxf(m, l[g]); }
        float s = 0.f, sl = 0.f;
        #pragma unroll
        for (int g = 0; g < 12; g++) {
            float e = expf(l[g] - m);
            s += e; sl += e * l[g];
        }
        float logZ = m + logf(s);
        int a = actions[warp];
        d_out[warp]        = v;
        d_out[2048 + warp] = (float)a;
        d_out[4096 + warp] = l[a] - logZ;
        d_out[6144 + warp] = logZ - sl / s;
    }
}

// ---------------------------------------------------------------------------
// Host launcher
// ---------------------------------------------------------------------------
#define C1_SMEM ((13*344           + 32*56 ) * 2)   // 12,528
#define C2_SMEM ((15*(44*40)       + 32*296) * 2)   // 71,744
#define C3_SMEM ((23*(23*40)       + 32*296) * 2)   // 61,264
#define C4_SMEM ((2*13*(13*40)     + 32*296) * 2)   // 45,984

extern "C" void kernel_launch(void* const* d_in, const int* in_sizes, int n_in,
                              void* d_out, int out_size) {
    const float* inputs = (const float*)d_in[0];
    const float* rnn_in = (const float*)d_in[1];
    const float* mask   = (const float*)d_in[2];
    const int*   actions= (const int*)  d_in[3];
    const float* w1 = (const float*)d_in[4];  const float* b1 = (const float*)d_in[5];
    const float* w2 = (const float*)d_in[6];  const float* b2 = (const float*)d_in[7];
    const float* w3 = (const float*)d_in[8];  const float* b3 = (const float*)d_in[9];
    const float* w4 = (const float*)d_in[10]; const float* b4 = (const float*)d_in[11];
    const float* W_ih = (const float*)d_in[12];
    const float* W_hh = (const float*)d_in[13];
    const float* b_ih = (const float*)d_in[14];
    const float* b_hh = (const float*)d_in[15];
    const float* Wc = (const float*)d_in[16]; const float* bc = (const float*)d_in[17];
    const float* Wa = (const float*)d_in[18]; const float* ba = (const float*)d_in[19];
    float* out = (float*)d_out;

    __half *a1, *a2, *a3, *xf;
    float *gi, *outs;
    cudaGetSymbolAddress((void**)&a1, g_a1);
    cudaGetSymbolAddress((void**)&a2, g_a2);
    cudaGetSymbolAddress((void**)&a3, g_a3);
    cudaGetSymbolAddress((void**)&xf, g_xf);
    cudaGetSymbolAddress((void**)&gi, g_gi);
    cudaGetSymbolAddress((void**)&outs, g_outs);

    cudaFuncSetAttribute((conv_f16<4,84,42,6,1,0,0>),   cudaFuncAttributeMaxDynamicSharedMemorySize, C1_SMEM);
    cudaFuncSetAttribute((conv_f16<32,42,21,7,1,1,0>),  cudaFuncAttributeMaxDynamicSharedMemorySize, C2_SMEM);
    cudaFuncSetAttribute((conv_f16<32,21,11,11,1,1,0>), cudaFuncAttributeMaxDynamicSharedMemorySize, C3_SMEM);
    cudaFuncSetAttribute((conv_f16<32,11,6,6,2,1,1>),   cudaFuncAttributeMaxDynamicSharedMemorySize, C4_SMEM);

    conv_f16<4,84,42,6,1,0,0>    <<<dim3(NTB,7), 256, C1_SMEM>>>(inputs, w1, b1, a1);
    conv_f16<32,42,21,7,1,1,0>   <<<dim3(NTB,3), 256, C2_SMEM>>>(a1, w2, b2, a2);
    conv_f16<32,21,11,11,1,1,0>  <<<dim3(NTB,1), 256, C3_SMEM>>>(a2, w3, b3, a3);
    conv_f16<32,11,6,6,2,1,1>    <<<dim3(NTB/2,1), 256, C4_SMEM>>>(a3, w4, b4, xf);

    gemm_f16<<<dim3(768/64, 2048/64), 256>>>(xf, W_ih, b_ih, gi);

    gru_kernel<<<GRU_BLOCKS, GRU_THREADS>>>(rnn_in, mask, W_hh, b_hh, gi, outs, out + 8192);

    heads_kernel<<<256, 256>>>(outs, actions, Wc, bc, Wa, ba, out);
}

// round 5
// speedup vs baseline: 4.4946x; 1.0522x over previous
#include <cuda_runtime.h>
#include <cuda_fp16.h>
#include <cstdint>

// ---------------------------------------------------------------------------
#define TT   64
#define BB   32
#define NTB  2048
#define HID  256
#define FEAT 1152

__device__ __half g_a1[2048u*32*42*42];   // NHWC f16
__device__ __half g_a2[2048u*32*21*21];   // NHWC f16
__device__ __half g_xf[2048u*1152];       // f16, reference feature order
__device__ float  g_gi[2048u*768];
__device__ float  g_outs[2048u*256];
__device__ float  g_h[2][BB*HID];
__device__ unsigned g_bar_cnt = 0;
__device__ unsigned g_bar_phase = 0;

// ---------------------------------------------------------------------------
__device__ __forceinline__ void mma16(float4& d, uint32_t a0, uint32_t a1,
                                      uint32_t a2, uint32_t a3,
                                      uint32_t b0, uint32_t b1) {
    asm volatile("mma.sync.aligned.m16n8k16.row.col.f32.f16.f16.f32 "
        "{%0,%1,%2,%3},{%4,%5,%6,%7},{%8,%9},{%0,%1,%2,%3};"
        : "+f"(d.x), "+f"(d.y), "+f"(d.z), "+f"(d.w)
        : "r"(a0), "r"(a1), "r"(a2), "r"(a3), "r"(b0), "r"(b1));
}
__device__ __forceinline__ float eluf(float x) { return x > 0.f ? x : expm1f(x); }

// ---------------------------------------------------------------------------
// fp16 implicit-GEMM conv3x3 stride2 pad1, OC=32, m16n8k16 (layers 1 & 2).
// ---------------------------------------------------------------------------
template<int IC, int IH, int OH, int BAND, int INMODE>
__global__ void __launch_bounds__(256) conv_f16(const void* __restrict__ in_,
        const float* __restrict__ wgt, const float* __restrict__ bias,
        void* __restrict__ out_)
{
    constexpr int OW = OH, IW = IH;
    constexpr bool C1 = (IC == 4);
    constexpr int XS = C1 ? 4 : 40;
    constexpr int RW = (IW+2)*XS;
    constexpr int ROWS = 2*BAND + 1;
    constexpr int SIN = ROWS*RW;
    constexpr int KS = C1 ? 3 : 18;
    constexpr int APAD = C1 ? 56 : 296;
    constexpr int NPIX = BAND*OW;
    constexpr int NT8 = (NPIX+7)/8;
    constexpr int NTW = (NT8+3)/4;
    constexpr int OHW = OH*OW;

    extern __shared__ __half sh[];
    __half* s_in = sh;
    __half* s_w  = sh + SIN;

    const int tid = threadIdx.x;
    const int n0 = blockIdx.x;
    const int oy0 = blockIdx.y * BAND;
    const int ybase = 2*oy0 - 1;

    for (int i = tid; i < SIN/8; i += 256) ((uint4*)s_in)[i] = make_uint4(0,0,0,0);

    if (C1) {
        for (int i = tid; i < 32*48; i += 256) {
            int oc = i/48, r = i - oc*48;
            int ky = r>>4, rr = r&15, kx = rr>>2, ic = rr&3;
            float v = (kx < 3) ? wgt[((oc*4+ic)*3+ky)*3+kx] : 0.f;
            s_w[oc*APAD + r] = __float2half_rn(v);
        }
    } else {
        for (int i = tid; i < 32*288; i += 256) {
            int oc = i/288, r = i - oc*288;
            int s = r>>4, c = r&15;
            int tap = s>>1, ch = s&1;
            int ky = tap/3, kx = tap - ky*3;
            s_w[oc*APAD + r] = __float2half_rn(wgt[((oc*32 + ch*16 + c)*3+ky)*3+kx]);
        }
    }

    const int y_lo = (ybase < 0) ? 0 : ybase;
    int y_hi = ybase + ROWS - 1; if (y_hi > IH-1) y_hi = IH-1;
    const int nrows = y_hi - y_lo + 1;

    if (INMODE == 0) {
        const float* inF = (const float*)in_;
        for (int i = tid; i < nrows*IW; i += 256) {
            int x = i % IW; int yy = i / IW; int y = y_lo + yy;
            const float* p = inF + (((size_t)n0*4)*IH + y)*IW + x;
            __half2 h01 = __floats2half2_rn(p[0], p[(size_t)IH*IW]);
            __half2 h23 = __floats2half2_rn(p[2*(size_t)IH*IW], p[3*(size_t)IH*IW]);
            __half* d = s_in + (y - ybase)*RW + (x+1)*4;
            *(__half2*)d = h01; *(__half2*)(d+2) = h23;
        }
    } else {
        const __half* inH = (const __half*)in_;
        for (int i = tid; i < nrows*IW*4; i += 256) {
            int g = i & 3, q = i >> 2;
            int x = q % IW; int yy = q / IW;
            int y = y_lo + yy;
            uint4 v = *(const uint4*)(inH + (((size_t)n0*IH + y)*IW + x)*32 + g*8);
            *(uint4*)(s_in + (y - ybase)*RW + (x+1)*40 + g*8) = v;
        }
    }
    __syncthreads();

    const int lane = tid & 31, warp = tid >> 5;
    const int m0 = (warp & 1)*16;
    const int ng = warp >> 1;
    const int gq = lane >> 2, tq = lane & 3;

    int pixbase[NTW];
    #pragma unroll
    for (int j = 0; j < NTW; j++) {
        int tile = ng + 4*j;
        int p = tile*8 + gq;
        int pp = (p < NPIX) ? p : 0;
        int dy = pp / OW, ox = pp - dy*OW;
        pixbase[j] = 2*dy*RW + 2*ox*XS + 2*tq;
    }

    float4 acc[NTW];
    #pragma unroll
    for (int j = 0; j < NTW; j++) acc[j] = make_float4(0.f,0.f,0.f,0.f);

    const __half* swr = s_w + (m0 + gq)*APAD + 2*tq;
    #pragma unroll
    for (int s = 0; s < KS; s++) {
        uint32_t a0 = *(const uint32_t*)(swr + s*16);
        uint32_t a1 = *(const uint32_t*)(swr + s*16 + 8*APAD);
        uint32_t a2 = *(const uint32_t*)(swr + s*16 + 8);
        uint32_t a3 = *(const uint32_t*)(swr + s*16 + 8*APAD + 8);
        int off;
        if (C1) { off = s*RW; }
        else { int tap = s>>1, ch = s&1; int ky = tap/3, kx = tap - ky*3;
               off = ky*RW + kx*40 + ch*16; }
        #pragma unroll
        for (int j = 0; j < NTW; j++) {
            const __half* bp = s_in + pixbase[j] + off;
            mma16(acc[j], a0, a1, a2, a3,
                  *(const uint32_t*)bp, *(const uint32_t*)(bp + 8));
        }
    }

    const int oc = m0 + gq;
    const float b0v = __ldg(&bias[oc]);
    const float b8v = __ldg(&bias[oc+8]);
    __half* ob0 = (__half*)out_ + ((size_t)n0*OHW + oy0*OW)*32;

    #pragma unroll
    for (int j = 0; j < NTW; j++) {
        int tile = ng + 4*j;
        if (tile >= NT8) continue;
        int pc = tile*8 + tq*2;
        if (pc < NPIX) {
            ob0[pc*32 + oc]   = __float2half_rn(eluf(acc[j].x + b0v));
            ob0[pc*32 + oc+8] = __float2half_rn(eluf(acc[j].z + b8v));
        }
        if (pc+1 < NPIX) {
            ob0[(pc+1)*32 + oc]   = __float2half_rn(eluf(acc[j].y + b0v));
            ob0[(pc+1)*32 + oc+8] = __float2half_rn(eluf(acc[j].w + b8v));
        }
    }
}

// ---------------------------------------------------------------------------
// Fused conv3 + conv4: one block per image. conv3 (21->11) writes its output
// tile to smem (slot layout + zero ring); conv4 (11->6) consumes it and writes
// xf in reference feature order (f16). No a3 global round-trip.
// ---------------------------------------------------------------------------
#define RW3  920          // 23 slots * 40
#define SIN3 (23*920)     // 21160
#define RW4  520          // 13 slots * 40
#define SIN4 (13*520)     // 6760
#define C34_SMEM ((SIN3 + SIN4 + 2*32*296) * 2)   // 93,728 B

__global__ void __launch_bounds__(256) conv34_f16(const __half* __restrict__ a2,
        const float* __restrict__ w3, const float* __restrict__ b3f,
        const float* __restrict__ w4, const float* __restrict__ b4f,
        __half* __restrict__ xf)
{
    extern __shared__ __half sh[];
    __half* s_in = sh;                    // conv3 input 23x23 slots
    __half* s_c4 = sh + SIN3;             // conv3 output / conv4 input 13x13 slots
    __half* s_w3 = sh + SIN3 + SIN4;
    __half* s_w4 = s_w3 + 32*296;

    const int tid = threadIdx.x;
    const int n = blockIdx.x;

    for (int i = tid; i < (SIN3+SIN4)/8; i += 256) ((uint4*)s_in)[i] = make_uint4(0,0,0,0);

    for (int i = tid; i < 32*288; i += 256) {
        int oc = i/288, r = i - oc*288;
        int s = r>>4, c = r&15;
        int tap = s>>1, ch = s&1;
        int ky = tap/3, kx = tap - ky*3;
        int widx = ((oc*32 + ch*16 + c)*3+ky)*3+kx;
        s_w3[oc*296 + r] = __float2half_rn(w3[widx]);
        s_w4[oc*296 + r] = __float2half_rn(w4[widx]);
    }

    // stage conv3 input: all 21 rows (ybase=-1 -> slot row y+1)
    for (int i = tid; i < 21*21*4; i += 256) {
        int g = i & 3, q = i >> 2;
        int x = q % 21; int y = q / 21;
        uint4 v = *(const uint4*)(a2 + (((size_t)n*21 + y)*21 + x)*32 + g*8);
        *(uint4*)(s_in + (y+1)*RW3 + (x+1)*40 + g*8) = v;
    }
    __syncthreads();

    const int lane = tid & 31, warp = tid >> 5;
    const int m0 = (warp & 1)*16;
    const int ng = warp >> 1;
    const int gq = lane >> 2, tq = lane & 3;
    const int oc = m0 + gq;

    // ---- conv3: NPIX=121, NT8=16, NTW=4 ----
    {
        int pixbase[4];
        #pragma unroll
        for (int j = 0; j < 4; j++) {
            int p = (ng + 4*j)*8 + gq;
            int pp = (p < 121) ? p : 0;
            int dy = pp / 11, ox = pp - dy*11;
            pixbase[j] = 2*dy*RW3 + 2*ox*40 + 2*tq;
        }
        float4 acc[4];
        #pragma unroll
        for (int j = 0; j < 4; j++) acc[j] = make_float4(0.f,0.f,0.f,0.f);

        const __half* swr = s_w3 + oc*296 + 2*tq;
        #pragma unroll
        for (int s = 0; s < 18; s++) {
            uint32_t a0 = *(const uint32_t*)(swr + s*16);
            uint32_t a1 = *(const uint32_t*)(swr + s*16 + 8*296);
            uint32_t a2r = *(const uint32_t*)(swr + s*16 + 8);
            uint32_t a3r = *(const uint32_t*)(swr + s*16 + 8*296 + 8);
            int tap = s>>1, ch = s&1; int ky = tap/3, kx = tap - ky*3;
            int off = ky*RW3 + kx*40 + ch*16;
            #pragma unroll
            for (int j = 0; j < 4; j++) {
                const __half* bp = s_in + pixbase[j] + off;
                mma16(acc[j], a0, a1, a2r, a3r,
                      *(const uint32_t*)bp, *(const uint32_t*)(bp + 8));
            }
        }
        const float b0v = __ldg(&b3f[oc]);
        const float b8v = __ldg(&b3f[oc+8]);
        #pragma unroll
        for (int j = 0; j < 4; j++) {
            int pc = (ng + 4*j)*8 + tq*2;
            #pragma unroll
            for (int u = 0; u < 2; u++) {
                int p = pc + u;
                if (p < 121) {
                    int y = p / 11, x = p - y*11;
                    __half* d = s_c4 + (y+1)*RW4 + (x+1)*40;
                    float v0 = (u == 0) ? acc[j].x : acc[j].y;
                    float v8 = (u == 0) ? acc[j].z : acc[j].w;
                    d[oc]   = __float2half_rn(eluf(v0 + b0v));
                    d[oc+8] = __float2half_rn(eluf(v8 + b8v));
                }
            }
        }
    }
    __syncthreads();

    // ---- conv4: NPIX=36, NT8=5, NTW=2 ----
    {
        int pixbase[2];
        #pragma unroll
        for (int j = 0; j < 2; j++) {
            int tile = ng + 4*j;
            int p = tile*8 + gq;
            int pp = (p < 36) ? p : 0;
            int dy = pp / 6, ox = pp - dy*6;
            pixbase[j] = 2*dy*RW4 + 2*ox*40 + 2*tq;
        }
        float4 acc[2];
        acc[0] = make_float4(0.f,0.f,0.f,0.f); acc[1] = acc[0];

        const __half* swr = s_w4 + oc*296 + 2*tq;
        #pragma unroll
        for (int s = 0; s < 18; s++) {
            uint32_t a0 = *(const uint32_t*)(swr + s*16);
            uint32_t a1 = *(const uint32_t*)(swr + s*16 + 8*296);
            uint32_t a2r = *(const uint32_t*)(swr + s*16 + 8);
            uint32_t a3r = *(const uint32_t*)(swr + s*16 + 8*296 + 8);
            int tap = s>>1, ch = s&1; int ky = tap/3, kx = tap - ky*3;
            int off = ky*RW4 + kx*40 + ch*16;
            #pragma unroll
            for (int j = 0; j < 2; j++) {
                const __half* bp = s_c4 + pixbase[j] + off;
                mma16(acc[j], a0, a1, a2r, a3r,
                      *(const uint32_t*)bp, *(const uint32_t*)(bp + 8));
            }
        }
        const float b0v = __ldg(&b4f[oc]);
        const float b8v = __ldg(&b4f[oc+8]);
        __half* ob = xf + (size_t)n*1152;
        #pragma unroll
        for (int j = 0; j < 2; j++) {
            int tile = ng + 4*j;
            if (tile >= 5) continue;
            int pc = tile*8 + tq*2;
            if (pc < 36) {
                ob[oc*36 + pc]     = __float2half_rn(eluf(acc[j].x + b0v));
                ob[(oc+8)*36 + pc] = __float2half_rn(eluf(acc[j].z + b8v));
            }
            if (pc+1 < 36) {
                ob[oc*36 + pc+1]     = __float2half_rn(eluf(acc[j].y + b0v));
                ob[(oc+8)*36 + pc+1] = __float2half_rn(eluf(acc[j].w + b8v));
            }
        }
    }
}

// ---------------------------------------------------------------------------
// gi[2048,768] = xf(f16) @ W_ih^T + b_ih    (f16 mma, f32 acc)
// ---------------------------------------------------------------------------
__global__ void __launch_bounds__(256) gemm_f16(const __half* __restrict__ A,
        const float* __restrict__ B, const float* __restrict__ bias,
        float* __restrict__ C)
{
    constexpr int ST = 40;
    __shared__ __half As[64*ST], Bs[64*ST];
    const int bm = blockIdx.y*64, bn = blockIdx.x*64;
    const int tid = threadIdx.x, lane = tid&31, warp = tid>>5;
    const int wm = (warp&1)*32, wn = (warp>>1)*16;
    const int gq = lane>>2, tq = lane&3;
    const int ldr = tid>>2, ldk = (tid&3)*8;

    float4 acc[2][2];
    #pragma unroll
    for (int i = 0; i < 2; i++)
        #pragma unroll
        for (int j = 0; j < 2; j++) acc[i][j] = make_float4(0.f,0.f,0.f,0.f);

    for (int k0 = 0; k0 < FEAT; k0 += 32) {
        uint4 av = *(const uint4*)(A + (size_t)(bm+ldr)*FEAT + k0 + ldk);
        *(uint4*)(As + ldr*ST + ldk) = av;
        float4 f0 = *(const float4*)(B + (size_t)(bn+ldr)*FEAT + k0 + ldk);
        float4 f1 = *(const float4*)(B + (size_t)(bn+ldr)*FEAT + k0 + ldk + 4);
        __half2 p0 = __floats2half2_rn(f0.x, f0.y);
        __half2 p1 = __floats2half2_rn(f0.z, f0.w);
        __half2 p2 = __floats2half2_rn(f1.x, f1.y);
        __half2 p3 = __floats2half2_rn(f1.z, f1.w);
        uint4 bvv;
        bvv.x = *(uint32_t*)&p0; bvv.y = *(uint32_t*)&p1;
        bvv.z = *(uint32_t*)&p2; bvv.w = *(uint32_t*)&p3;
        *(uint4*)(Bs + ldr*ST + ldk) = bvv;
        __syncthreads();
        #pragma unroll
        for (int s = 0; s < 2; s++) {
            #pragma unroll
            for (int mi = 0; mi < 2; mi++) {
                const __half* ap = As + (wm + mi*16 + gq)*ST + s*16 + 2*tq;
                uint32_t a0 = *(const uint32_t*)ap;
                uint32_t a1 = *(const uint32_t*)(ap + 8*ST);
                uint32_t a2 = *(const uint32_t*)(ap + 8);
                uint32_t a3 = *(const uint32_t*)(ap + 8*ST + 8);
                #pragma unroll
                for (int ni = 0; ni < 2; ni++) {
                    const __half* bp = Bs + (wn + ni*8 + gq)*ST + s*16 + 2*tq;
                    mma16(acc[mi][ni], a0, a1, a2, a3,
                          *(const uint32_t*)bp, *(const uint32_t*)(bp + 8));
                }
            }
        }
        __syncthreads();
    }
    #pragma unroll
    for (int mi = 0; mi < 2; mi++) {
        #pragma unroll
        for (int ni = 0; ni < 2; ni++) {
            int row = bm + wm + mi*16 + gq;
            int col = bn + wn + ni*8 + tq*2;
            float bb0 = __ldg(&bias[col]), bb1 = __ldg(&bias[col+1]);
            C[(size_t)row*768 + col]       = acc[mi][ni].x + bb0;
            C[(size_t)row*768 + col + 1]   = acc[mi][ni].y + bb1;
            C[(size_t)(row+8)*768 + col]   = acc[mi][ni].z + bb0;
            C[(size_t)(row+8)*768 + col+1] = acc[mi][ni].w + bb1;
        }
    }
}

// ---------------------------------------------------------------------------
// Persistent GRU: 64 blocks x 256 threads, k-split x2.
// Thread (half, gj, b) computes 3 partial dots over k in [half*128, half*128+128),
// partials combined via smem; 2 warps/SMSP hide LDS latency.
// ---------------------------------------------------------------------------
#define GRU_BLOCKS 64
#define GRU_THREADS 256

__device__ __forceinline__ void grid_barrier(unsigned target) {
    __threadfence();
    __syncthreads();
    if (threadIdx.x == 0) {
        unsigned v = atomicAdd(&g_bar_cnt, 1);
        if (v == GRU_BLOCKS - 1) {
            g_bar_cnt = 0;
            __threadfence();
            atomicAdd(&g_bar_phase, 1);
        } else {
            while ((int)(*(volatile unsigned*)&g_bar_phase - target) < 0) { __nanosleep(16); }
        }
        __threadfence();
    }
    __syncthreads();
}

__global__ void gru_kernel(const float* __restrict__ rnn_in, const float* __restrict__ mask,
                           const float* __restrict__ W_hh, const float* __restrict__ b_hh,
                           const float* __restrict__ gi_all, float* __restrict__ outs,
                           float* __restrict__ hfin) {
    __shared__ float s_w[12*260];
    __shared__ float s_h[32*260];
    __shared__ float s_p[3*256];

    const int tid = threadIdx.x;
    const int bx  = blockIdx.x;

    for (int i = tid; i < 12*64; i += GRU_THREADS) {
        int rl = i >> 6, kq = i & 63;
        int gate = rl >> 2, gj2 = rl & 3;
        float4 w = *(const float4*)&W_hh[(size_t)(gate*256 + bx*4 + gj2)*256 + kq*4];
        *(float4*)&s_w[rl*260 + kq*4] = w;
    }
    if (bx == 0) {
        for (int i = tid; i < BB*HID; i += GRU_THREADS) g_h[0][i] = rnn_in[i];
    }
    unsigned tgt = *(volatile unsigned*)&g_bar_phase;
    grid_barrier(++tgt);

    const int half = tid >> 7;          // k-split
    const int r    = tid & 127;         // (gj, b)
    const int gj = r >> 5, b = r & 31;
    const int g = bx*4 + gj;
    const float br = __ldg(&b_hh[g]);
    const float bz = __ldg(&b_hh[256 + g]);
    const float bn = __ldg(&b_hh[512 + g]);

    for (int t = 0; t < TT; t++) {
        const float* hprev = g_h[t & 1];
        for (int i = tid; i < 32*64; i += GRU_THREADS) {
            int bb = i >> 6, kq = i & 63;
            float m = __ldg(&mask[t*32 + bb]);
            float4 hv = __ldcg((const float4*)&hprev[bb*256 + kq*4]);
            hv.x *= m; hv.y *= m; hv.z *= m; hv.w *= m;
            *(float4*)&s_h[bb*260 + kq*4] = hv;
        }
        __syncthreads();
        float4 ar = make_float4(0.f,0.f,0.f,0.f), az = ar, an = ar;
        const float4* h4  = (const float4*)&s_h[b*260 + half*128];
        const float4* wr4 = (const float4*)&s_w[(0 + gj)*260 + half*128];
        const float4* wz4 = (const float4*)&s_w[(4 + gj)*260 + half*128];
        const float4* wn4 = (const float4*)&s_w[(8 + gj)*260 + half*128];
        #pragma unroll 8
        for (int kq = 0; kq < 32; kq++) {
            float4 h = h4[kq];
            float4 wr = wr4[kq], wz = wz4[kq], wn = wn4[kq];
            ar.x += h.x*wr.x; ar.y += h.y*wr.y; ar.z += h.z*wr.z; ar.w += h.w*wr.w;
            az.x += h.x*wz.x; az.y += h.y*wz.y; az.z += h.z*wz.z; az.w += h.w*wz.w;
            an.x += h.x*wn.x; an.y += h.y*wn.y; an.z += h.z*wn.z; an.w += h.w*wn.w;
        }
        s_p[0*256 + tid] = ar.x + ar.y + ar.z + ar.w;
        s_p[1*256 + tid] = az.x + az.y + az.z + az.w;
        s_p[2*256 + tid] = an.x + an.y + an.z + an.w;
        __syncthreads();
        if (tid < 128) {
            float ghr = s_p[0*256 + tid] + s_p[0*256 + tid + 128] + br;
            float ghz = s_p[1*256 + tid] + s_p[1*256 + tid + 128] + bz;
            float ghn = s_p[2*256 + tid] + s_p[2*256 + tid + 128] + bn;
            const float* gi = gi_all + (size_t)(t*32 + b)*768;
            float rr = 1.f / (1.f + expf(-(__ldg(&gi[g])       + ghr)));
            float zz = 1.f / (1.f + expf(-(__ldg(&gi[256 + g]) + ghz)));
            float nn = tanhf(__ldg(&gi[512 + g]) + rr*ghn);
            float hold = s_h[b*260 + g];
            float hn = (1.f - zz)*nn + zz*hold;
            g_h[(t + 1) & 1][b*256 + g] = hn;
            outs[(size_t)(t*32 + b)*256 + g] = hn;
            if (t == TT - 1) hfin[b*256 + g] = hn;
        }
        grid_barrier(++tgt);
    }
}

// ---------------------------------------------------------------------------
// Heads
// ---------------------------------------------------------------------------
__global__ void heads_kernel(const float* __restrict__ outs, const int* __restrict__ actions,
                             const float* __restrict__ Wc, const float* __restrict__ bc,
                             const float* __restrict__ Wa, const float* __restrict__ ba,
                             float* __restrict__ d_out) {
    int warp = (blockIdx.x * blockDim.x + threadIdx.x) >> 5;
    int lane = threadIdx.x & 31;
    if (warp >= NTB) return;
    const float* o = outs + (size_t)warp * 256;

    float acc[13];
    #pragma unroll
    for (int g = 0; g < 13; g++) acc[g] = 0.f;
    #pragma unroll
    for (int i = 0; i < 8; i++) {
        int k = lane + 32*i;
        float x = o[k];
        acc[0] += x * __ldg(&Wc[k]);
        #pragma unroll
        for (int g = 0; g < 12; g++) acc[1 + g] += x * __ldg(&Wa[g*256 + k]);
    }
    #pragma unroll
    for (int g = 0; g < 13; g++) {
        #pragma unroll
        for (int s = 16; s > 0; s >>= 1) acc[g] += __shfl_xor_sync(0xFFFFFFFFu, acc[g], s);
    }
    if (lane == 0) {
        float v = acc[0] + bc[0];
        float l[12];
        float m = -1e30f;
        #pragma unroll
        for (int g = 0; g < 12; g++) { l[g] = acc[1 + g] + ba[g]; m = fmaxf(m, l[g]); }
        float s = 0.f, sl = 0.f;
        #pragma unroll
        for (int g = 0; g < 12; g++) {
            float e = expf(l[g] - m);
            s += e; sl += e * l[g];
        }
        float logZ = m + logf(s);
        int a = actions[warp];
        d_out[warp]        = v;
        d_out[2048 + warp] = (float)a;
        d_out[4096 + warp] = l[a] - logZ;
        d_out[6144 + warp] = logZ - sl / s;
    }
}

// ---------------------------------------------------------------------------
// Host launcher
// ---------------------------------------------------------------------------
#define C1_SMEM ((13*344      + 32*56 ) * 2)   // 12,528
#define C2_SMEM ((15*(44*40)  + 32*296) * 2)   // 71,744

extern "C" void kernel_launch(void* const* d_in, const int* in_sizes, int n_in,
                              void* d_out, int out_size) {
    const float* inputs = (const float*)d_in[0];
    const float* rnn_in = (const float*)d_in[1];
    const float* mask   = (const float*)d_in[2];
    const int*   actions= (const int*)  d_in[3];
    const float* w1 = (const float*)d_in[4];  const float* b1 = (const float*)d_in[5];
    const float* w2 = (const float*)d_in[6];  const float* b2 = (const float*)d_in[7];
    const float* w3 = (const float*)d_in[8];  const float* b3 = (const float*)d_in[9];
    const float* w4 = (const float*)d_in[10]; const float* b4 = (const float*)d_in[11];
    const float* W_ih = (const float*)d_in[12];
    const float* W_hh = (const float*)d_in[13];
    const float* b_ih = (const float*)d_in[14];
    const float* b_hh = (const float*)d_in[15];
    const float* Wc = (const float*)d_in[16]; const float* bc = (const float*)d_in[17];
    const float* Wa = (const float*)d_in[18]; const float* ba = (const float*)d_in[19];
    float* out = (float*)d_out;

    __half *a1, *a2, *xf;
    float *gi, *outs;
    cudaGetSymbolAddress((void**)&a1, g_a1);
    cudaGetSymbolAddress((void**)&a2, g_a2);
    cudaGetSymbolAddress((void**)&xf, g_xf);
    cudaGetSymbolAddress((void**)&gi, g_gi);
    cudaGetSymbolAddress((void**)&outs, g_outs);

    cudaFuncSetAttribute((conv_f16<4,84,42,6,0>),  cudaFuncAttributeMaxDynamicSharedMemorySize, C1_SMEM);
    cudaFuncSetAttribute((conv_f16<32,42,21,7,1>), cudaFuncAttributeMaxDynamicSharedMemorySize, C2_SMEM);
    cudaFuncSetAttribute(conv34_f16,               cudaFuncAttributeMaxDynamicSharedMemorySize, C34_SMEM);

    conv_f16<4,84,42,6,0>  <<<dim3(NTB,7), 256, C1_SMEM>>>(inputs, w1, b1, a1);
    conv_f16<32,42,21,7,1> <<<dim3(NTB,3), 256, C2_SMEM>>>(a1, w2, b2, a2);
    conv34_f16             <<<NTB, 256, C34_SMEM>>>(a2, w3, b3, w4, b4, xf);

    gemm_f16<<<dim3(768/64, 2048/64), 256>>>(xf, W_ih, b_ih, gi);

    gru_kernel<<<GRU_BLOCKS, GRU_THREADS>>>(rnn_in, mask, W_hh, b_hh, gi, outs, out + 8192);

    heads_kernel<<<256, 256>>>(outs, actions, Wc, bc, Wa, ba, out);
}